// round 11
// baseline (speedup 1.0000x reference)
#include <cuda_runtime.h>
#include <cuda_bf16.h>
#include <cuda_pipeline.h>
#include <mma.h>
#include <math.h>

#define BB 4
#define DIM 384
#define QKV_CH 1152
#define HW_ 16384
#define CC_ 48
#define NPART 768

namespace wx = nvcuda::wmma;

static __device__ __nv_bfloat16 g_tmpb[(size_t)BB * QKV_CH * HW_];
static __device__ __nv_bfloat16 g_vb[(size_t)BB * DIM * HW_];
static __device__ __nv_bfloat16 g_xb[(size_t)BB * DIM * HW_];
static __device__ __nv_bfloat16 g_wqb[(size_t)QKV_CH * DIM];
static __device__ float g_part[(size_t)BB * NPART * 80];
static __device__ float g_attn[BB * 64];
static __device__ __nv_bfloat16 g_weffb[(size_t)BB * DIM * DIM];

__global__ __launch_bounds__(256) void kc_conv_x(const float* __restrict__ src, int off)
{
    int i = off + blockIdx.x * 256 + threadIdx.x;
    float4 v = ((const float4*)src)[i];
    ((__nv_bfloat162*)g_xb)[2 * i] = __floats2bfloat162_rn(v.x, v.y);
    ((__nv_bfloat162*)g_xb)[2 * i + 1] = __floats2bfloat162_rn(v.z, v.w);
}

__global__ __launch_bounds__(256) void kc_conv_w(const float* __restrict__ src)
{
    int i = blockIdx.x * 256 + threadIdx.x;
    float4 v = ((const float4*)src)[i];
    ((__nv_bfloat162*)g_wqb)[2 * i] = __floats2bfloat162_rn(v.x, v.y);
    ((__nv_bfloat162*)g_wqb)[2 * i + 1] = __floats2bfloat162_rn(v.z, v.w);
}

// 4-stage cp.async bf16 wmma GEMM.
// Block tile 128x256, 256 threads (8 warps), warp tile 64x64 (16 acc fragments:
// 2x MMA per fragment-load and 2x ILP vs 64x32). K-tile 32, 12 iters,
// ONE __syncthreads per iter.
// Stage (27136 B): A 128x32 pitch 40 bf16 (10240 B) + B 32x256 pitch 264 bf16 (16896 B).
// 4 stages = 108544 B dynamic smem; 1 CTA/SM (regs ~200 bind anyway).
// Epilogue: per-warp 16x64 f32 staging (32 KB total) aliases stage memory.
__device__ __forceinline__ void gemm_body(
    const __nv_bfloat16* __restrict__ Ab,
    const __nv_bfloat16* __restrict__ Bb,
    const float* __restrict__ bias,
    const float* __restrict__ rbase,
    float* __restrict__ ob,
    __nv_bfloat16* __restrict__ ob16)
{
    extern __shared__ __align__(16) char sbuf[];

    const int row0 = blockIdx.y * 128;
    const int col0 = blockIdx.x * 256;

    const int tid = threadIdx.x;
    const int lane = tid & 31;
    const int wid = tid >> 5;
    const int wm = wid & 1;
    const int wn = wid >> 1;

    // A copy coords: 512 16B-chunks (2/thread). chunk c: row c>>2, quad c&3.
    const int ar0 = tid >> 2;
    const int aq0 = tid & 3;
    // B copy coords: 1024 16B-chunks (4/thread). chunk c: row c>>5, off c&31.
    const int br0 = tid >> 5;
    const int bo0 = tid & 31;

    char* a_dst0 = sbuf + ar0 * 80 + aq0 * 16;
    char* a_dst1 = sbuf + (ar0 + 64) * 80 + aq0 * 16;
    char* b_dst0 = sbuf + 10240 + br0 * 528 + bo0 * 16;
    char* b_dst1 = sbuf + 10240 + (br0 + 8) * 528 + bo0 * 16;
    char* b_dst2 = sbuf + 10240 + (br0 + 16) * 528 + bo0 * 16;
    char* b_dst3 = sbuf + 10240 + (br0 + 24) * 528 + bo0 * 16;

    const __nv_bfloat16* a_src0 = Ab + (size_t)(row0 + ar0) * DIM + aq0 * 8;
    const __nv_bfloat16* a_src1 = a_src0 + (size_t)64 * DIM;
    const __nv_bfloat16* b_src0 = Bb + (size_t)br0 * HW_ + col0 + bo0 * 8;
    const __nv_bfloat16* b_src1 = b_src0 + (size_t)8 * HW_;
    const __nv_bfloat16* b_src2 = b_src0 + (size_t)16 * HW_;
    const __nv_bfloat16* b_src3 = b_src0 + (size_t)24 * HW_;

    wx::fragment<wx::accumulator, 16, 16, 16, float> c[4][4];
    for (int i = 0; i < 4; i++)
        for (int j = 0; j < 4; j++)
            wx::fill_fragment(c[i][j], 0.0f);

    // Prologue: fill stages 0,1,2
    for (int s = 0; s < 3; s++) {
        int off = s * 27136;
        int koff = s * 32;
        __pipeline_memcpy_async(a_dst0 + off, a_src0 + koff, 16);
        __pipeline_memcpy_async(a_dst1 + off, a_src1 + koff, 16);
        __pipeline_memcpy_async(b_dst0 + off, b_src0 + (size_t)koff * HW_, 16);
        __pipeline_memcpy_async(b_dst1 + off, b_src1 + (size_t)koff * HW_, 16);
        __pipeline_memcpy_async(b_dst2 + off, b_src2 + (size_t)koff * HW_, 16);
        __pipeline_memcpy_async(b_dst3 + off, b_src3 + (size_t)koff * HW_, 16);
        __pipeline_commit();
    }

    for (int kt = 0; kt < 12; kt++) {
        if (kt < 10) {
            __pipeline_wait_prior(2);
        } else if (kt == 10) {
            __pipeline_wait_prior(1);
        } else {
            __pipeline_wait_prior(0);
        }
        __syncthreads();

        if (kt < 9) {
            int off = ((kt + 3) & 3) * 27136;
            int koff = (kt + 3) * 32;
            __pipeline_memcpy_async(a_dst0 + off, a_src0 + koff, 16);
            __pipeline_memcpy_async(a_dst1 + off, a_src1 + koff, 16);
            __pipeline_memcpy_async(b_dst0 + off, b_src0 + (size_t)koff * HW_, 16);
            __pipeline_memcpy_async(b_dst1 + off, b_src1 + (size_t)koff * HW_, 16);
            __pipeline_memcpy_async(b_dst2 + off, b_src2 + (size_t)koff * HW_, 16);
            __pipeline_memcpy_async(b_dst3 + off, b_src3 + (size_t)koff * HW_, 16);
            __pipeline_commit();
        }

        const __nv_bfloat16* As = (const __nv_bfloat16*)(sbuf + (kt & 3) * 27136);
        const __nv_bfloat16* Bs = (const __nv_bfloat16*)(sbuf + (kt & 3) * 27136 + 10240);

        for (int ks = 0; ks < 2; ks++) {
            wx::fragment<wx::matrix_a, 16, 16, 16, __nv_bfloat16, wx::row_major> a[4];
            for (int i = 0; i < 4; i++)
                wx::load_matrix_sync(a[i], As + (wm * 64 + i * 16) * 40 + ks * 16, 40);
            for (int j = 0; j < 4; j++) {
                wx::fragment<wx::matrix_b, 16, 16, 16, __nv_bfloat16, wx::row_major> bf;
                wx::load_matrix_sync(bf, Bs + (ks * 16) * 264 + wn * 64 + j * 16, 264);
                for (int i = 0; i < 4; i++)
                    wx::mma_sync(c[i][j], a[i], bf, c[i][j]);
            }
        }
    }
    __syncthreads();

    // Epilogue: per-warp 16x64 f32 staging tile
    float* Csw = (float*)sbuf + wid * 1024;

    for (int i = 0; i < 4; i++) {
        for (int j = 0; j < 4; j++)
            wx::store_matrix_sync(Csw + j * 16, c[i][j], 64, wx::mem_row_major);
        __syncwarp();
        int r = lane >> 1;
        int ch = (lane & 1) * 32;
        int gr = row0 + wm * 64 + i * 16 + r;
        int gc = col0 + wn * 64 + ch;
        float bi = bias[gr];
        for (int q = 0; q < 32; q += 4) {
            float4 v;
            v.x = Csw[r * 64 + ch + q] + bi;
            v.y = Csw[r * 64 + ch + q + 1] + bi;
            v.z = Csw[r * 64 + ch + q + 2] + bi;
            v.w = Csw[r * 64 + ch + q + 3] + bi;
            if (ob16) {
                __nv_bfloat162* op16 = (__nv_bfloat162*)(ob16 + (size_t)gr * HW_ + gc + q);
                op16[0] = __floats2bfloat162_rn(v.x, v.y);
                op16[1] = __floats2bfloat162_rn(v.z, v.w);
            } else {
                if (rbase) {
                    const float* rp = rbase + (size_t)gr * HW_ + gc + q;
                    float4 xv = *(const float4*)(rp);
                    v.x += xv.x;
                    v.y += xv.y;
                    v.z += xv.z;
                    v.w += xv.w;
                }
                *(float4*)(ob + (size_t)gr * HW_ + gc + q) = v;
            }
        }
        __syncwarp();
    }
}

__global__ __launch_bounds__(256) void k1_gemm(const float* __restrict__ b_qkv)
{
    const int b = blockIdx.z;
    const float* nores = 0;
    float* noout = 0;
    gemm_body(g_wqb, g_xb + (size_t)b * DIM * HW_, b_qkv, nores, noout,
              g_tmpb + (size_t)b * QKV_CH * HW_);
}

__global__ __launch_bounds__(256) void k5_gemm(
    const float* __restrict__ b_proj, const float* __restrict__ x,
    float* __restrict__ out)
{
    const int b = blockIdx.z;
    __nv_bfloat16* no16 = 0;
    gemm_body(g_weffb + (size_t)b * DIM * DIM, g_vb + (size_t)b * DIM * HW_,
              b_proj, x + (size_t)b * DIM * HW_, out + (size_t)b * DIM * HW_, no16);
}

__device__ __forceinline__ float warp_red(float v)
{
    v += __shfl_down_sync(0xffffffffu, v, 16);
    v += __shfl_down_sync(0xffffffffu, v, 8);
    v += __shfl_down_sync(0xffffffffu, v, 4);
    v += __shfl_down_sync(0xffffffffu, v, 2);
    v += __shfl_down_sync(0xffffffffu, v, 1);
    return v;
}

// Fused dwconv(q,k) + Gram/norm partial reductions.
__global__ __launch_bounds__(256) void k2qk(
    const float* __restrict__ w_dw, const float* __restrict__ b_dw)
{
    const int b = blockIdx.z;
    const int cc = blockIdx.y;
    const int strip = blockIdx.x;
    const int y0 = strip * 8;

    __shared__ __align__(16) char sqk[46080];
    __shared__ float sw[16][9];
    __shared__ float sbias[16];

    __nv_bfloat16* sm = (__nv_bfloat16*)sqk;
    const __nv_bfloat16* tb = g_tmpb + (size_t)b * QKV_CH * HW_;

    for (int idx = threadIdx.x; idx < 2560; idx += 256) {
        int ch = idx / 160;
        int rem = idx - ch * 160;
        int row = rem >> 4;
        int u = rem & 15;
        int gy = y0 - 1 + row;
        uint4 v;
        v.x = 0u; v.y = 0u; v.z = 0u; v.w = 0u;
        if (gy >= 0 && gy < 128) {
            int chg = ch * 48 + cc;
            if (ch >= 8) chg = 384 + (ch - 8) * 48 + cc;
            v = *(const uint4*)(tb + (size_t)chg * HW_ + gy * 128 + u * 8);
        }
        *(uint4*)(sm + ((ch * 10 + row) * 144 + 8 + u * 8)) = v;
    }
    for (int idx = threadIdx.x; idx < 320; idx += 256) {
        int ch = idx / 20;
        int rem = idx - ch * 20;
        int row = rem >> 1;
        int col = 7;
        if (rem & 1) col = 136;
        sm[(ch * 10 + row) * 144 + col] = __float2bfloat16(0.f);
    }
    if (threadIdx.x < 144) {
        int ci = threadIdx.x / 9;
        int j = threadIdx.x - ci * 9;
        int chg = ci * 48 + cc;
        if (ci >= 8) chg = 384 + (ci - 8) * 48 + cc;
        sw[ci][j] = w_dw[chg * 9 + j];
    }
    if (threadIdx.x >= 144 && threadIdx.x < 160) {
        int ci = threadIdx.x - 144;
        int chg = ci * 48 + cc;
        if (ci >= 8) chg = 384 + (ci - 8) * 48 + cc;
        sbias[ci] = b_dw[chg];
    }
    __syncthreads();

    const int r = threadIdx.x >> 5;
    const int x0 = (threadIdx.x & 31) * 4;

    float acc[8][8];
    float aq[8];
    float ak[8];
    float qo[8][4];
    #pragma unroll
    for (int n = 0; n < 8; n++) {
        aq[n] = 0.f;
        ak[n] = 0.f;
        #pragma unroll
        for (int m = 0; m < 8; m++) acc[n][m] = 0.f;
    }

    #pragma unroll
    for (int n = 0; n < 8; n++) {
        float v0[8];
        float v1[8];
        float v2[8];
        #pragma unroll
        for (int j = 0; j < 4; j++) {
            int base0 = (n * 10 + r) * 144 + 6 + x0 + 2 * j;
            float2 f0 = __bfloat1622float2(*(const __nv_bfloat162*)(sm + base0));
            float2 f1 = __bfloat1622float2(*(const __nv_bfloat162*)(sm + base0 + 144));
            float2 f2 = __bfloat1622float2(*(const __nv_bfloat162*)(sm + base0 + 288));
            v0[2 * j] = f0.x; v0[2 * j + 1] = f0.y;
            v1[2 * j] = f1.x; v1[2 * j + 1] = f1.y;
            v2[2 * j] = f2.x; v2[2 * j + 1] = f2.y;
        }
        float bi = sbias[n];
        #pragma unroll
        for (int i = 0; i < 4; i++) {
            float o = bi;
            o += sw[n][0] * v0[1 + i];
            o += sw[n][1] * v0[2 + i];
            o += sw[n][2] * v0[3 + i];
            o += sw[n][3] * v1[1 + i];
            o += sw[n][4] * v1[2 + i];
            o += sw[n][5] * v1[3 + i];
            o += sw[n][6] * v2[1 + i];
            o += sw[n][7] * v2[2 + i];
            o += sw[n][8] * v2[3 + i];
            qo[n][i] = o;
            aq[n] += o * o;
        }
    }

    #pragma unroll
    for (int m = 0; m < 8; m++) {
        float v0[8];
        float v1[8];
        float v2[8];
        #pragma unroll
        for (int j = 0; j < 4; j++) {
            int base0 = ((8 + m) * 10 + r) * 144 + 6 + x0 + 2 * j;
            float2 f0 = __bfloat1622float2(*(const __nv_bfloat162*)(sm + base0));
            float2 f1 = __bfloat1622float2(*(const __nv_bfloat162*)(sm + base0 + 144));
            float2 f2 = __bfloat1622float2(*(const __nv_bfloat162*)(sm + base0 + 288));
            v0[2 * j] = f0.x; v0[2 * j + 1] = f0.y;
            v1[2 * j] = f1.x; v1[2 * j + 1] = f1.y;
            v2[2 * j] = f2.x; v2[2 * j + 1] = f2.y;
        }
        float bi = sbias[8 + m];
        float ko[4];
        #pragma unroll
        for (int i = 0; i < 4; i++) {
            float o = bi;
            o += sw[8 + m][0] * v0[1 + i];
            o += sw[8 + m][1] * v0[2 + i];
            o += sw[8 + m][2] * v0[3 + i];
            o += sw[8 + m][3] * v1[1 + i];
            o += sw[8 + m][4] * v1[2 + i];
            o += sw[8 + m][5] * v1[3 + i];
            o += sw[8 + m][6] * v2[1 + i];
            o += sw[8 + m][7] * v2[2 + i];
            o += sw[8 + m][8] * v2[3 + i];
            ko[i] = o;
            ak[m] += o * o;
        }
        #pragma unroll
        for (int n = 0; n < 8; n++) {
            #pragma unroll
            for (int i = 0; i < 4; i++) acc[n][m] += qo[n][i] * ko[i];
        }
    }

    __syncthreads();
    float* red = (float*)sqk;
    const int lane = threadIdx.x & 31;
    const int wid = threadIdx.x >> 5;
    #pragma unroll
    for (int n = 0; n < 8; n++) {
        #pragma unroll
        for (int m = 0; m < 8; m++) {
            float s = warp_red(acc[n][m]);
            if (lane == 0) red[wid * 80 + n * 8 + m] = s;
        }
        float s1 = warp_red(aq[n]);
        if (lane == 0) red[wid * 80 + 64 + n] = s1;
        float s2 = warp_red(ak[n]);
        if (lane == 0) red[wid * 80 + 72 + n] = s2;
    }
    __syncthreads();
    if (threadIdx.x < 80) {
        float t = 0.f;
        #pragma unroll
        for (int w = 0; w < 8; w++) t += red[w * 80 + threadIdx.x];
        g_part[((size_t)b * NPART + cc * 16 + strip) * 80 + threadIdx.x] = t;
    }
}

// dwconv for v channels only -> g_vb (bf16)
__global__ __launch_bounds__(256) void k2v(
    const float* __restrict__ w_dw, const float* __restrict__ b_dw)
{
    const int chv = blockIdx.y;
    const int ch = 768 + chv;
    const int b = blockIdx.z;
    const int y0 = blockIdx.x * 16;

    __shared__ __align__(16) __nv_bfloat16 smv[18 * 144];
    const __nv_bfloat16* src = g_tmpb + ((size_t)b * QKV_CH + ch) * HW_;

    for (int idx = threadIdx.x; idx < 288; idx += 256) {
        int row = idx >> 4;
        int u = idx & 15;
        int gy = y0 - 1 + row;
        uint4 v;
        v.x = 0u; v.y = 0u; v.z = 0u; v.w = 0u;
        if (gy >= 0 && gy < 128) v = *(const uint4*)(src + gy * 128 + u * 8);
        *(uint4*)(smv + (row * 144 + 8 + u * 8)) = v;
    }
    if (threadIdx.x < 36) {
        int row = threadIdx.x >> 1;
        int col = 7;
        if (threadIdx.x & 1) col = 136;
        smv[row * 144 + col] = __float2bfloat16(0.f);
    }
    __syncthreads();

    float wv[9];
    #pragma unroll
    for (int i = 0; i < 9; i++) wv[i] = w_dw[ch * 9 + i];
    float bi = b_dw[ch];

    const int r = threadIdx.x >> 4;
    const int x0 = (threadIdx.x & 15) * 8;

    float v0[12];
    float v1[12];
    float v2[12];
    #pragma unroll
    for (int j = 0; j < 6; j++) {
        int base0 = r * 144 + 6 + x0 + 2 * j;
        float2 f0 = __bfloat1622float2(*(const __nv_bfloat162*)(smv + base0));
        float2 f1 = __bfloat1622float2(*(const __nv_bfloat162*)(smv + base0 + 144));
        float2 f2 = __bfloat1622float2(*(const __nv_bfloat162*)(smv + base0 + 288));
        v0[2 * j] = f0.x; v0[2 * j + 1] = f0.y;
        v1[2 * j] = f1.x; v1[2 * j + 1] = f1.y;
        v2[2 * j] = f2.x; v2[2 * j + 1] = f2.y;
    }

    float o[8];
    #pragma unroll
    for (int i = 0; i < 8; i++) {
        float t = bi;
        t += wv[0] * v0[1 + i];
        t += wv[1] * v0[2 + i];
        t += wv[2] * v0[3 + i];
        t += wv[3] * v1[1 + i];
        t += wv[4] * v1[2 + i];
        t += wv[5] * v1[3 + i];
        t += wv[6] * v2[1 + i];
        t += wv[7] * v2[2 + i];
        t += wv[8] * v2[3 + i];
        o[i] = t;
    }

    const int p = (y0 + r) * 128 + x0;
    __nv_bfloat162* dst = (__nv_bfloat162*)(g_vb + ((size_t)b * DIM + chv) * HW_ + p);
    dst[0] = __floats2bfloat162_rn(o[0], o[1]);
    dst[1] = __floats2bfloat162_rn(o[2], o[3]);
    dst[2] = __floats2bfloat162_rn(o[4], o[5]);
    dst[3] = __floats2bfloat162_rn(o[6], o[7]);
}

__global__ __launch_bounds__(640) void k4a_softmax(const float* __restrict__ temperature)
{
    const int b = blockIdx.x;
    __shared__ float red[80];

    const int e = threadIdx.x >> 3;
    const int j = threadIdx.x & 7;
    float t = 0.f;
    for (int s = j; s < NPART; s += 8)
        t += g_part[((size_t)b * NPART + s) * 80 + e];
    t += __shfl_down_sync(0xffffffffu, t, 4);
    t += __shfl_down_sync(0xffffffffu, t, 2);
    t += __shfl_down_sync(0xffffffffu, t, 1);
    if (j == 0) red[e] = t;
    __syncthreads();

    if (threadIdx.x < 8) {
        const int n = threadIdx.x;
        const float temp = temperature[0];
        float qn = fmaxf(sqrtf(red[64 + n]), 1e-12f);
        float logit[8];
        float mx = -1e30f;
        #pragma unroll
        for (int m = 0; m < 8; m++) {
            float kn = fmaxf(sqrtf(red[72 + m]), 1e-12f);
            float l = temp * red[n * 8 + m] / (qn * kn);
            logit[m] = l;
            mx = fmaxf(mx, l);
        }
        float sum = 0.f;
        float ex[8];
        #pragma unroll
        for (int m = 0; m < 8; m++) {
            ex[m] = expf(logit[m] - mx);
            sum += ex[m];
        }
        float inv = 1.f / sum;
        #pragma unroll
        for (int m = 0; m < 8; m++) g_attn[b * 64 + n * 8 + m] = ex[m] * inv;
    }
}

__global__ __launch_bounds__(256) void k4b_weff(const float* __restrict__ w_proj)
{
    const int b = blockIdx.y;
    __shared__ float at[64];
    if (threadIdx.x < 64) at[threadIdx.x] = g_attn[b * 64 + threadIdx.x];
    __syncthreads();

    const int idx = blockIdx.x * 256 + threadIdx.x;
    const int co = idx / DIM;
    const int jj = idx % DIM;
    const int m = jj / CC_;
    const int cc = jj % CC_;
    float s = 0.f;
    #pragma unroll
    for (int n = 0; n < 8; n++)
        s += at[n * 8 + m] * __ldg(&w_proj[co * DIM + n * CC_ + cc]);
    g_weffb[(size_t)b * DIM * DIM + idx] = __float2bfloat16(s);
}

extern "C" void kernel_launch(void* const* d_in, const int* in_sizes, int n_in,
                              void* d_out, int out_size)
{
    const float* x = (const float*)d_in[0];
    const float* temp = (const float*)d_in[1];
    const float* w_qkv = (const float*)d_in[2];
    const float* b_qkv = (const float*)d_in[3];
    const float* w_dw = (const float*)d_in[4];
    const float* b_dw = (const float*)d_in[5];
    const float* w_proj = (const float*)d_in[6];
    const float* b_proj = (const float*)d_in[7];
    float* out = (float*)d_out;

    int smem_gemm = 108544;
    cudaFuncSetAttribute(k1_gemm, cudaFuncAttributeMaxDynamicSharedMemorySize, smem_gemm);
    cudaFuncSetAttribute(k5_gemm, cudaFuncAttributeMaxDynamicSharedMemorySize, smem_gemm);

    int gcx = 12288;
    int half = 3145728;
    int gcw = 432;
    dim3 g1(64, 9, 4);
    dim3 gqk(16, 48, 4);
    dim3 gv(8, 384, 4);
    dim3 g4b(576, 4);
    dim3 g5(64, 3, 4);
    int nb4 = 4;
    int zero = 0;

    kc_conv_x<<<gcx, 256>>>(x, zero);
    kc_conv_x<<<gcx, 256>>>(x, half);
    kc_conv_w<<<gcw, 256>>>(w_qkv);
    k1_gemm<<<g1, 256, smem_gemm>>>(b_qkv);
    k2qk<<<gqk, 256>>>(w_dw, b_dw);
    k2v<<<gv, 256>>>(w_dw, b_dw);
    k4a_softmax<<<nb4, 640>>>(temp);
    k4b_weff<<<g4b, 256>>>(w_proj);
    k5_gemm<<<g5, 256, smem_gemm>>>(b_proj, x, out);
}

// round 12
// speedup vs baseline: 1.0012x; 1.0012x over previous
#include <cuda_runtime.h>
#include <cuda_bf16.h>
#include <cuda_pipeline.h>
#include <mma.h>
#include <math.h>

#define BB 4
#define DIM 384
#define QKV_CH 1152
#define HW_ 16384
#define CC_ 48
#define NPART 768

namespace wx = nvcuda::wmma;

static __device__ __nv_bfloat16 g_tmpb[(size_t)BB * QKV_CH * HW_];
static __device__ __nv_bfloat16 g_vb[(size_t)BB * DIM * HW_];
static __device__ __nv_bfloat16 g_xb[(size_t)BB * DIM * HW_];
static __device__ __nv_bfloat16 g_wqb[(size_t)QKV_CH * DIM];
static __device__ float g_part[(size_t)BB * NPART * 80];
static __device__ float g_attn[BB * 64];
static __device__ __nv_bfloat16 g_weffb[(size_t)BB * DIM * DIM];

__global__ __launch_bounds__(256) void kc_conv_x(const float* __restrict__ src, int off)
{
    int i = off + blockIdx.x * 256 + threadIdx.x;
    float4 v = ((const float4*)src)[i];
    ((__nv_bfloat162*)g_xb)[2 * i] = __floats2bfloat162_rn(v.x, v.y);
    ((__nv_bfloat162*)g_xb)[2 * i + 1] = __floats2bfloat162_rn(v.z, v.w);
}

__global__ __launch_bounds__(256) void kc_conv_w(const float* __restrict__ src)
{
    int i = blockIdx.x * 256 + threadIdx.x;
    float4 v = ((const float4*)src)[i];
    ((__nv_bfloat162*)g_wqb)[2 * i] = __floats2bfloat162_rn(v.x, v.y);
    ((__nv_bfloat162*)g_wqb)[2 * i + 1] = __floats2bfloat162_rn(v.z, v.w);
}

// 4-stage cp.async bf16 wmma GEMM.
// Block tile 128x256, 256 threads (8 warps), warp tile 64x64 (16 acc fragments:
// 2x MMA per fragment-load and 2x ILP vs 64x32). K-tile 32, 12 iters,
// ONE __syncthreads per iter.
// Stage (27136 B): A 128x32 pitch 40 bf16 (10240 B) + B 32x256 pitch 264 bf16 (16896 B).
// 4 stages = 108544 B dynamic smem; 1 CTA/SM (regs ~200 bind anyway).
// Epilogue: per-warp 16x64 f32 staging (32 KB total) aliases stage memory.
__device__ __forceinline__ void gemm_body(
    const __nv_bfloat16* __restrict__ Ab,
    const __nv_bfloat16* __restrict__ Bb,
    const float* __restrict__ bias,
    const float* __restrict__ rbase,
    float* __restrict__ ob,
    __nv_bfloat16* __restrict__ ob16)
{
    extern __shared__ __align__(16) char sbuf[];

    const int row0 = blockIdx.y * 128;
    const int col0 = blockIdx.x * 256;

    const int tid = threadIdx.x;
    const int lane = tid & 31;
    const int wid = tid >> 5;
    const int wm = wid & 1;
    const int wn = wid >> 1;

    // A copy coords: 512 16B-chunks (2/thread). chunk c: row c>>2, quad c&3.
    const int ar0 = tid >> 2;
    const int aq0 = tid & 3;
    // B copy coords: 1024 16B-chunks (4/thread). chunk c: row c>>5, off c&31.
    const int br0 = tid >> 5;
    const int bo0 = tid & 31;

    char* a_dst0 = sbuf + ar0 * 80 + aq0 * 16;
    char* a_dst1 = sbuf + (ar0 + 64) * 80 + aq0 * 16;
    char* b_dst0 = sbuf + 10240 + br0 * 528 + bo0 * 16;
    char* b_dst1 = sbuf + 10240 + (br0 + 8) * 528 + bo0 * 16;
    char* b_dst2 = sbuf + 10240 + (br0 + 16) * 528 + bo0 * 16;
    char* b_dst3 = sbuf + 10240 + (br0 + 24) * 528 + bo0 * 16;

    const __nv_bfloat16* a_src0 = Ab + (size_t)(row0 + ar0) * DIM + aq0 * 8;
    const __nv_bfloat16* a_src1 = a_src0 + (size_t)64 * DIM;
    const __nv_bfloat16* b_src0 = Bb + (size_t)br0 * HW_ + col0 + bo0 * 8;
    const __nv_bfloat16* b_src1 = b_src0 + (size_t)8 * HW_;
    const __nv_bfloat16* b_src2 = b_src0 + (size_t)16 * HW_;
    const __nv_bfloat16* b_src3 = b_src0 + (size_t)24 * HW_;

    wx::fragment<wx::accumulator, 16, 16, 16, float> c[4][4];
    for (int i = 0; i < 4; i++)
        for (int j = 0; j < 4; j++)
            wx::fill_fragment(c[i][j], 0.0f);

    // Prologue: fill stages 0,1,2
    for (int s = 0; s < 3; s++) {
        int off = s * 27136;
        int koff = s * 32;
        __pipeline_memcpy_async(a_dst0 + off, a_src0 + koff, 16);
        __pipeline_memcpy_async(a_dst1 + off, a_src1 + koff, 16);
        __pipeline_memcpy_async(b_dst0 + off, b_src0 + (size_t)koff * HW_, 16);
        __pipeline_memcpy_async(b_dst1 + off, b_src1 + (size_t)koff * HW_, 16);
        __pipeline_memcpy_async(b_dst2 + off, b_src2 + (size_t)koff * HW_, 16);
        __pipeline_memcpy_async(b_dst3 + off, b_src3 + (size_t)koff * HW_, 16);
        __pipeline_commit();
    }

    for (int kt = 0; kt < 12; kt++) {
        if (kt < 10) {
            __pipeline_wait_prior(2);
        } else if (kt == 10) {
            __pipeline_wait_prior(1);
        } else {
            __pipeline_wait_prior(0);
        }
        __syncthreads();

        if (kt < 9) {
            int off = ((kt + 3) & 3) * 27136;
            int koff = (kt + 3) * 32;
            __pipeline_memcpy_async(a_dst0 + off, a_src0 + koff, 16);
            __pipeline_memcpy_async(a_dst1 + off, a_src1 + koff, 16);
            __pipeline_memcpy_async(b_dst0 + off, b_src0 + (size_t)koff * HW_, 16);
            __pipeline_memcpy_async(b_dst1 + off, b_src1 + (size_t)koff * HW_, 16);
            __pipeline_memcpy_async(b_dst2 + off, b_src2 + (size_t)koff * HW_, 16);
            __pipeline_memcpy_async(b_dst3 + off, b_src3 + (size_t)koff * HW_, 16);
            __pipeline_commit();
        }

        const __nv_bfloat16* As = (const __nv_bfloat16*)(sbuf + (kt & 3) * 27136);
        const __nv_bfloat16* Bs = (const __nv_bfloat16*)(sbuf + (kt & 3) * 27136 + 10240);

        for (int ks = 0; ks < 2; ks++) {
            wx::fragment<wx::matrix_a, 16, 16, 16, __nv_bfloat16, wx::row_major> a[4];
            for (int i = 0; i < 4; i++)
                wx::load_matrix_sync(a[i], As + (wm * 64 + i * 16) * 40 + ks * 16, 40);
            for (int j = 0; j < 4; j++) {
                wx::fragment<wx::matrix_b, 16, 16, 16, __nv_bfloat16, wx::row_major> bf;
                wx::load_matrix_sync(bf, Bs + (ks * 16) * 264 + wn * 64 + j * 16, 264);
                for (int i = 0; i < 4; i++)
                    wx::mma_sync(c[i][j], a[i], bf, c[i][j]);
            }
        }
    }
    __syncthreads();

    // Epilogue: per-warp 16x64 f32 staging tile
    float* Csw = (float*)sbuf + wid * 1024;

    for (int i = 0; i < 4; i++) {
        for (int j = 0; j < 4; j++)
            wx::store_matrix_sync(Csw + j * 16, c[i][j], 64, wx::mem_row_major);
        __syncwarp();
        int r = lane >> 1;
        int ch = (lane & 1) * 32;
        int gr = row0 + wm * 64 + i * 16 + r;
        int gc = col0 + wn * 64 + ch;
        float bi = bias[gr];
        for (int q = 0; q < 32; q += 4) {
            float4 v;
            v.x = Csw[r * 64 + ch + q] + bi;
            v.y = Csw[r * 64 + ch + q + 1] + bi;
            v.z = Csw[r * 64 + ch + q + 2] + bi;
            v.w = Csw[r * 64 + ch + q + 3] + bi;
            if (ob16) {
                __nv_bfloat162* op16 = (__nv_bfloat162*)(ob16 + (size_t)gr * HW_ + gc + q);
                op16[0] = __floats2bfloat162_rn(v.x, v.y);
                op16[1] = __floats2bfloat162_rn(v.z, v.w);
            } else {
                if (rbase) {
                    const float* rp = rbase + (size_t)gr * HW_ + gc + q;
                    float4 xv = *(const float4*)(rp);
                    v.x += xv.x;
                    v.y += xv.y;
                    v.z += xv.z;
                    v.w += xv.w;
                }
                *(float4*)(ob + (size_t)gr * HW_ + gc + q) = v;
            }
        }
        __syncwarp();
    }
}

__global__ __launch_bounds__(256) void k1_gemm(const float* __restrict__ b_qkv)
{
    const int b = blockIdx.z;
    const float* nores = 0;
    float* noout = 0;
    gemm_body(g_wqb, g_xb + (size_t)b * DIM * HW_, b_qkv, nores, noout,
              g_tmpb + (size_t)b * QKV_CH * HW_);
}

__global__ __launch_bounds__(256) void k5_gemm(
    const float* __restrict__ b_proj, const float* __restrict__ x,
    float* __restrict__ out)
{
    const int b = blockIdx.z;
    __nv_bfloat16* no16 = 0;
    gemm_body(g_weffb + (size_t)b * DIM * DIM, g_vb + (size_t)b * DIM * HW_,
              b_proj, x + (size_t)b * DIM * HW_, out + (size_t)b * DIM * HW_, no16);
}

__device__ __forceinline__ float warp_red(float v)
{
    v += __shfl_down_sync(0xffffffffu, v, 16);
    v += __shfl_down_sync(0xffffffffu, v, 8);
    v += __shfl_down_sync(0xffffffffu, v, 4);
    v += __shfl_down_sync(0xffffffffu, v, 2);
    v += __shfl_down_sync(0xffffffffu, v, 1);
    return v;
}

// Fused dwconv(q,k) + Gram/norm partial reductions.
__global__ __launch_bounds__(256) void k2qk(
    const float* __restrict__ w_dw, const float* __restrict__ b_dw)
{
    const int b = blockIdx.z;
    const int cc = blockIdx.y;
    const int strip = blockIdx.x;
    const int y0 = strip * 8;

    __shared__ __align__(16) char sqk[46080];
    __shared__ float sw[16][9];
    __shared__ float sbias[16];

    __nv_bfloat16* sm = (__nv_bfloat16*)sqk;
    const __nv_bfloat16* tb = g_tmpb + (size_t)b * QKV_CH * HW_;

    for (int idx = threadIdx.x; idx < 2560; idx += 256) {
        int ch = idx / 160;
        int rem = idx - ch * 160;
        int row = rem >> 4;
        int u = rem & 15;
        int gy = y0 - 1 + row;
        uint4 v;
        v.x = 0u; v.y = 0u; v.z = 0u; v.w = 0u;
        if (gy >= 0 && gy < 128) {
            int chg = ch * 48 + cc;
            if (ch >= 8) chg = 384 + (ch - 8) * 48 + cc;
            v = *(const uint4*)(tb + (size_t)chg * HW_ + gy * 128 + u * 8);
        }
        *(uint4*)(sm + ((ch * 10 + row) * 144 + 8 + u * 8)) = v;
    }
    for (int idx = threadIdx.x; idx < 320; idx += 256) {
        int ch = idx / 20;
        int rem = idx - ch * 20;
        int row = rem >> 1;
        int col = 7;
        if (rem & 1) col = 136;
        sm[(ch * 10 + row) * 144 + col] = __float2bfloat16(0.f);
    }
    if (threadIdx.x < 144) {
        int ci = threadIdx.x / 9;
        int j = threadIdx.x - ci * 9;
        int chg = ci * 48 + cc;
        if (ci >= 8) chg = 384 + (ci - 8) * 48 + cc;
        sw[ci][j] = w_dw[chg * 9 + j];
    }
    if (threadIdx.x >= 144 && threadIdx.x < 160) {
        int ci = threadIdx.x - 144;
        int chg = ci * 48 + cc;
        if (ci >= 8) chg = 384 + (ci - 8) * 48 + cc;
        sbias[ci] = b_dw[chg];
    }
    __syncthreads();

    const int r = threadIdx.x >> 5;
    const int x0 = (threadIdx.x & 31) * 4;

    float acc[8][8];
    float aq[8];
    float ak[8];
    float qo[8][4];
    #pragma unroll
    for (int n = 0; n < 8; n++) {
        aq[n] = 0.f;
        ak[n] = 0.f;
        #pragma unroll
        for (int m = 0; m < 8; m++) acc[n][m] = 0.f;
    }

    #pragma unroll
    for (int n = 0; n < 8; n++) {
        float v0[8];
        float v1[8];
        float v2[8];
        #pragma unroll
        for (int j = 0; j < 4; j++) {
            int base0 = (n * 10 + r) * 144 + 6 + x0 + 2 * j;
            float2 f0 = __bfloat1622float2(*(const __nv_bfloat162*)(sm + base0));
            float2 f1 = __bfloat1622float2(*(const __nv_bfloat162*)(sm + base0 + 144));
            float2 f2 = __bfloat1622float2(*(const __nv_bfloat162*)(sm + base0 + 288));
            v0[2 * j] = f0.x; v0[2 * j + 1] = f0.y;
            v1[2 * j] = f1.x; v1[2 * j + 1] = f1.y;
            v2[2 * j] = f2.x; v2[2 * j + 1] = f2.y;
        }
        float bi = sbias[n];
        #pragma unroll
        for (int i = 0; i < 4; i++) {
            float o = bi;
            o += sw[n][0] * v0[1 + i];
            o += sw[n][1] * v0[2 + i];
            o += sw[n][2] * v0[3 + i];
            o += sw[n][3] * v1[1 + i];
            o += sw[n][4] * v1[2 + i];
            o += sw[n][5] * v1[3 + i];
            o += sw[n][6] * v2[1 + i];
            o += sw[n][7] * v2[2 + i];
            o += sw[n][8] * v2[3 + i];
            qo[n][i] = o;
            aq[n] += o * o;
        }
    }

    #pragma unroll
    for (int m = 0; m < 8; m++) {
        float v0[8];
        float v1[8];
        float v2[8];
        #pragma unroll
        for (int j = 0; j < 4; j++) {
            int base0 = ((8 + m) * 10 + r) * 144 + 6 + x0 + 2 * j;
            float2 f0 = __bfloat1622float2(*(const __nv_bfloat162*)(sm + base0));
            float2 f1 = __bfloat1622float2(*(const __nv_bfloat162*)(sm + base0 + 144));
            float2 f2 = __bfloat1622float2(*(const __nv_bfloat162*)(sm + base0 + 288));
            v0[2 * j] = f0.x; v0[2 * j + 1] = f0.y;
            v1[2 * j] = f1.x; v1[2 * j + 1] = f1.y;
            v2[2 * j] = f2.x; v2[2 * j + 1] = f2.y;
        }
        float bi = sbias[8 + m];
        float ko[4];
        #pragma unroll
        for (int i = 0; i < 4; i++) {
            float o = bi;
            o += sw[8 + m][0] * v0[1 + i];
            o += sw[8 + m][1] * v0[2 + i];
            o += sw[8 + m][2] * v0[3 + i];
            o += sw[8 + m][3] * v1[1 + i];
            o += sw[8 + m][4] * v1[2 + i];
            o += sw[8 + m][5] * v1[3 + i];
            o += sw[8 + m][6] * v2[1 + i];
            o += sw[8 + m][7] * v2[2 + i];
            o += sw[8 + m][8] * v2[3 + i];
            ko[i] = o;
            ak[m] += o * o;
        }
        #pragma unroll
        for (int n = 0; n < 8; n++) {
            #pragma unroll
            for (int i = 0; i < 4; i++) acc[n][m] += qo[n][i] * ko[i];
        }
    }

    __syncthreads();
    float* red = (float*)sqk;
    const int lane = threadIdx.x & 31;
    const int wid = threadIdx.x >> 5;
    #pragma unroll
    for (int n = 0; n < 8; n++) {
        #pragma unroll
        for (int m = 0; m < 8; m++) {
            float s = warp_red(acc[n][m]);
            if (lane == 0) red[wid * 80 + n * 8 + m] = s;
        }
        float s1 = warp_red(aq[n]);
        if (lane == 0) red[wid * 80 + 64 + n] = s1;
        float s2 = warp_red(ak[n]);
        if (lane == 0) red[wid * 80 + 72 + n] = s2;
    }
    __syncthreads();
    if (threadIdx.x < 80) {
        float t = 0.f;
        #pragma unroll
        for (int w = 0; w < 8; w++) t += red[w * 80 + threadIdx.x];
        g_part[((size_t)b * NPART + cc * 16 + strip) * 80 + threadIdx.x] = t;
    }
}

// dwconv for v channels only -> g_vb (bf16)
__global__ __launch_bounds__(256) void k2v(
    const float* __restrict__ w_dw, const float* __restrict__ b_dw)
{
    const int chv = blockIdx.y;
    const int ch = 768 + chv;
    const int b = blockIdx.z;
    const int y0 = blockIdx.x * 16;

    __shared__ __align__(16) __nv_bfloat16 smv[18 * 144];
    const __nv_bfloat16* src = g_tmpb + ((size_t)b * QKV_CH + ch) * HW_;

    for (int idx = threadIdx.x; idx < 288; idx += 256) {
        int row = idx >> 4;
        int u = idx & 15;
        int gy = y0 - 1 + row;
        uint4 v;
        v.x = 0u; v.y = 0u; v.z = 0u; v.w = 0u;
        if (gy >= 0 && gy < 128) v = *(const uint4*)(src + gy * 128 + u * 8);
        *(uint4*)(smv + (row * 144 + 8 + u * 8)) = v;
    }
    if (threadIdx.x < 36) {
        int row = threadIdx.x >> 1;
        int col = 7;
        if (threadIdx.x & 1) col = 136;
        smv[row * 144 + col] = __float2bfloat16(0.f);
    }
    __syncthreads();

    float wv[9];
    #pragma unroll
    for (int i = 0; i < 9; i++) wv[i] = w_dw[ch * 9 + i];
    float bi = b_dw[ch];

    const int r = threadIdx.x >> 4;
    const int x0 = (threadIdx.x & 15) * 8;

    float v0[12];
    float v1[12];
    float v2[12];
    #pragma unroll
    for (int j = 0; j < 6; j++) {
        int base0 = r * 144 + 6 + x0 + 2 * j;
        float2 f0 = __bfloat1622float2(*(const __nv_bfloat162*)(smv + base0));
        float2 f1 = __bfloat1622float2(*(const __nv_bfloat162*)(smv + base0 + 144));
        float2 f2 = __bfloat1622float2(*(const __nv_bfloat162*)(smv + base0 + 288));
        v0[2 * j] = f0.x; v0[2 * j + 1] = f0.y;
        v1[2 * j] = f1.x; v1[2 * j + 1] = f1.y;
        v2[2 * j] = f2.x; v2[2 * j + 1] = f2.y;
    }

    float o[8];
    #pragma unroll
    for (int i = 0; i < 8; i++) {
        float t = bi;
        t += wv[0] * v0[1 + i];
        t += wv[1] * v0[2 + i];
        t += wv[2] * v0[3 + i];
        t += wv[3] * v1[1 + i];
        t += wv[4] * v1[2 + i];
        t += wv[5] * v1[3 + i];
        t += wv[6] * v2[1 + i];
        t += wv[7] * v2[2 + i];
        t += wv[8] * v2[3 + i];
        o[i] = t;
    }

    const int p = (y0 + r) * 128 + x0;
    __nv_bfloat162* dst = (__nv_bfloat162*)(g_vb + ((size_t)b * DIM + chv) * HW_ + p);
    dst[0] = __floats2bfloat162_rn(o[0], o[1]);
    dst[1] = __floats2bfloat162_rn(o[2], o[3]);
    dst[2] = __floats2bfloat162_rn(o[4], o[5]);
    dst[3] = __floats2bfloat162_rn(o[6], o[7]);
}

__global__ __launch_bounds__(640) void k4a_softmax(const float* __restrict__ temperature)
{
    const int b = blockIdx.x;
    __shared__ float red[80];

    const int e = threadIdx.x >> 3;
    const int j = threadIdx.x & 7;
    float t = 0.f;
    for (int s = j; s < NPART; s += 8)
        t += g_part[((size_t)b * NPART + s) * 80 + e];
    t += __shfl_down_sync(0xffffffffu, t, 4);
    t += __shfl_down_sync(0xffffffffu, t, 2);
    t += __shfl_down_sync(0xffffffffu, t, 1);
    if (j == 0) red[e] = t;
    __syncthreads();

    if (threadIdx.x < 8) {
        const int n = threadIdx.x;
        const float temp = temperature[0];
        float qn = fmaxf(sqrtf(red[64 + n]), 1e-12f);
        float logit[8];
        float mx = -1e30f;
        #pragma unroll
        for (int m = 0; m < 8; m++) {
            float kn = fmaxf(sqrtf(red[72 + m]), 1e-12f);
            float l = temp * red[n * 8 + m] / (qn * kn);
            logit[m] = l;
            mx = fmaxf(mx, l);
        }
        float sum = 0.f;
        float ex[8];
        #pragma unroll
        for (int m = 0; m < 8; m++) {
            ex[m] = expf(logit[m] - mx);
            sum += ex[m];
        }
        float inv = 1.f / sum;
        #pragma unroll
        for (int m = 0; m < 8; m++) g_attn[b * 64 + n * 8 + m] = ex[m] * inv;
    }
}

__global__ __launch_bounds__(256) void k4b_weff(const float* __restrict__ w_proj)
{
    const int b = blockIdx.y;
    __shared__ float at[64];
    if (threadIdx.x < 64) at[threadIdx.x] = g_attn[b * 64 + threadIdx.x];
    __syncthreads();

    const int idx = blockIdx.x * 256 + threadIdx.x;
    const int co = idx / DIM;
    const int jj = idx % DIM;
    const int m = jj / CC_;
    const int cc = jj % CC_;
    float s = 0.f;
    #pragma unroll
    for (int n = 0; n < 8; n++)
        s += at[n * 8 + m] * __ldg(&w_proj[co * DIM + n * CC_ + cc]);
    g_weffb[(size_t)b * DIM * DIM + idx] = __float2bfloat16(s);
}

extern "C" void kernel_launch(void* const* d_in, const int* in_sizes, int n_in,
                              void* d_out, int out_size)
{
    const float* x = (const float*)d_in[0];
    const float* temp = (const float*)d_in[1];
    const float* w_qkv = (const float*)d_in[2];
    const float* b_qkv = (const float*)d_in[3];
    const float* w_dw = (const float*)d_in[4];
    const float* b_dw = (const float*)d_in[5];
    const float* w_proj = (const float*)d_in[6];
    const float* b_proj = (const float*)d_in[7];
    float* out = (float*)d_out;

    int smem_gemm = 108544;
    cudaFuncSetAttribute(k1_gemm, cudaFuncAttributeMaxDynamicSharedMemorySize, smem_gemm);
    cudaFuncSetAttribute(k5_gemm, cudaFuncAttributeMaxDynamicSharedMemorySize, smem_gemm);

    int gcx = 12288;
    int half = 3145728;
    int gcw = 432;
    dim3 g1(64, 9, 4);
    dim3 gqk(16, 48, 4);
    dim3 gv(8, 384, 4);
    dim3 g4b(576, 4);
    dim3 g5(64, 3, 4);
    int nb4 = 4;
    int zero = 0;

    kc_conv_x<<<gcx, 256>>>(x, zero);
    kc_conv_x<<<gcx, 256>>>(x, half);
    kc_conv_w<<<gcw, 256>>>(w_qkv);
    k1_gemm<<<g1, 256, smem_gemm>>>(b_qkv);
    k2qk<<<gqk, 256>>>(w_dw, b_dw);
    k2v<<<gv, 256>>>(w_dw, b_dw);
    k4a_softmax<<<nb4, 640>>>(temp);
    k4b_weff<<<g4b, 256>>>(w_proj);
    k5_gemm<<<g5, 256, smem_gemm>>>(b_proj, x, out);
}

// round 13
// speedup vs baseline: 1.1166x; 1.1153x over previous
#include <cuda_runtime.h>
#include <cuda_bf16.h>
#include <cuda_pipeline.h>
#include <mma.h>
#include <math.h>

#define BB 4
#define DIM 384
#define QKV_CH 1152
#define HW_ 16384
#define CC_ 48
#define NPART 3072

namespace wx = nvcuda::wmma;

static __device__ __nv_bfloat16 g_tmpb[(size_t)BB * QKV_CH * HW_];
static __device__ __nv_bfloat16 g_vb[(size_t)BB * DIM * HW_];
static __device__ __nv_bfloat16 g_xb[(size_t)BB * DIM * HW_];
static __device__ __nv_bfloat16 g_wqb[(size_t)QKV_CH * DIM];
static __device__ float g_part[(size_t)BB * NPART * 80];
static __device__ float g_attn[BB * 64];
static __device__ __nv_bfloat16 g_weffb[(size_t)BB * DIM * DIM];

__global__ __launch_bounds__(256) void kc_conv_x(const float* __restrict__ src)
{
    int i = blockIdx.x * 256 + threadIdx.x;
    float4 v = ((const float4*)src)[i];
    ((__nv_bfloat162*)g_xb)[2 * i] = __floats2bfloat162_rn(v.x, v.y);
    ((__nv_bfloat162*)g_xb)[2 * i + 1] = __floats2bfloat162_rn(v.z, v.w);
}

__global__ __launch_bounds__(256) void kc_conv_w(const float* __restrict__ src)
{
    int i = blockIdx.x * 256 + threadIdx.x;
    float4 v = ((const float4*)src)[i];
    ((__nv_bfloat162*)g_wqb)[2 * i] = __floats2bfloat162_rn(v.x, v.y);
    ((__nv_bfloat162*)g_wqb)[2 * i + 1] = __floats2bfloat162_rn(v.z, v.w);
}

// R7 GEMM body (proven best): 2-stage cp.async, 128x128 tile, 256 thr, static smem.
__device__ __forceinline__ void gemm_body(
    const __nv_bfloat16* __restrict__ Ab,
    const __nv_bfloat16* __restrict__ Bb,
    const float* __restrict__ bias,
    const float* __restrict__ rbase,
    float* __restrict__ ob,
    __nv_bfloat16* __restrict__ ob16)
{
    __shared__ __align__(16) char sbuf[37888];

    const int row0 = blockIdx.y * 128;
    const int col0 = blockIdx.x * 128;

    const int tid = threadIdx.x;
    const int lane = tid & 31;
    const int wid = tid >> 5;
    const int wm = wid & 1;
    const int wn = wid >> 1;

    const int ar = tid >> 2;
    const int acol = (tid & 3) * 8;
    const int br = tid >> 4;
    const int bcol = (tid & 15) * 8;

    char* a_dst0 = sbuf + ar * 80 + acol * 2;
    char* a_dst1 = sbuf + (ar + 64) * 80 + acol * 2;
    char* b_dst0 = sbuf + 10240 + br * 272 + bcol * 2;
    char* b_dst1 = sbuf + 10240 + (br + 16) * 272 + bcol * 2;

    wx::fragment<wx::accumulator, 16, 16, 16, float> c[4][2];
    for (int i = 0; i < 4; i++)
        for (int j = 0; j < 2; j++)
            wx::fill_fragment(c[i][j], 0.0f);

    const __nv_bfloat16* a_src0 = Ab + (size_t)(row0 + ar) * DIM + acol;
    const __nv_bfloat16* a_src1 = a_src0 + (size_t)64 * DIM;
    const __nv_bfloat16* b_src0 = Bb + (size_t)br * HW_ + col0 + bcol;
    const __nv_bfloat16* b_src1 = b_src0 + (size_t)16 * HW_;

    __pipeline_memcpy_async(a_dst0, a_src0, 16);
    __pipeline_memcpy_async(a_dst1, a_src1, 16);
    __pipeline_memcpy_async(b_dst0, b_src0, 16);
    __pipeline_memcpy_async(b_dst1, b_src1, 16);
    __pipeline_commit();

    for (int kt = 0; kt < 12; kt++) {
        if (kt < 11) {
            int nb = (kt + 1) & 1;
            int koff = (kt + 1) * 32;
            __pipeline_memcpy_async(a_dst0 + nb * 18944, a_src0 + koff, 16);
            __pipeline_memcpy_async(a_dst1 + nb * 18944, a_src1 + koff, 16);
            __pipeline_memcpy_async(b_dst0 + nb * 18944, b_src0 + (size_t)koff * HW_, 16);
            __pipeline_memcpy_async(b_dst1 + nb * 18944, b_src1 + (size_t)koff * HW_, 16);
            __pipeline_commit();
            __pipeline_wait_prior(1);
        } else {
            __pipeline_wait_prior(0);
        }
        __syncthreads();

        const __nv_bfloat16* As = (const __nv_bfloat16*)(sbuf + (kt & 1) * 18944);
        const __nv_bfloat16* Bs = (const __nv_bfloat16*)(sbuf + (kt & 1) * 18944 + 10240);

        for (int ks = 0; ks < 2; ks++) {
            wx::fragment<wx::matrix_a, 16, 16, 16, __nv_bfloat16, wx::row_major> a[4];
            wx::fragment<wx::matrix_b, 16, 16, 16, __nv_bfloat16, wx::row_major> bf[2];
            for (int i = 0; i < 4; i++)
                wx::load_matrix_sync(a[i], As + (wm * 64 + i * 16) * 40 + ks * 16, 40);
            for (int j = 0; j < 2; j++)
                wx::load_matrix_sync(bf[j], Bs + (ks * 16) * 136 + wn * 32 + j * 16, 136);
            for (int i = 0; i < 4; i++)
                for (int j = 0; j < 2; j++)
                    wx::mma_sync(c[i][j], a[i], bf[j], c[i][j]);
        }
        __syncthreads();
    }

    float* Csw = (float*)sbuf + wid * 512;

    for (int i = 0; i < 4; i++) {
        wx::store_matrix_sync(Csw, c[i][0], 32, wx::mem_row_major);
        wx::store_matrix_sync(Csw + 16, c[i][1], 32, wx::mem_row_major);
        __syncwarp();
        int r = lane >> 1;
        int cb = (lane & 1) * 16;
        int gr = row0 + wm * 64 + i * 16 + r;
        int gc = col0 + wn * 32 + cb;
        float bi = bias[gr];
        for (int q = 0; q < 16; q += 4) {
            float4 v;
            v.x = Csw[r * 32 + cb + q] + bi;
            v.y = Csw[r * 32 + cb + q + 1] + bi;
            v.z = Csw[r * 32 + cb + q + 2] + bi;
            v.w = Csw[r * 32 + cb + q + 3] + bi;
            if (ob16) {
                __nv_bfloat162* op16 = (__nv_bfloat162*)(ob16 + (size_t)gr * HW_ + gc);
                op16[(q >> 1)] = __floats2bfloat162_rn(v.x, v.y);
                op16[(q >> 1) + 1] = __floats2bfloat162_rn(v.z, v.w);
            } else {
                if (rbase) {
                    const float* rp = rbase + (size_t)gr * HW_ + gc + q;
                    float4 xv = *(const float4*)(rp);
                    v.x += xv.x;
                    v.y += xv.y;
                    v.z += xv.z;
                    v.w += xv.w;
                }
                *(float4*)(ob + (size_t)gr * HW_ + gc + q) = v;
            }
        }
        __syncwarp();
    }
}

__global__ __launch_bounds__(256) void k1_gemm(const float* __restrict__ b_qkv)
{
    const int b = blockIdx.z;
    const float* nores = 0;
    float* noout = 0;
    gemm_body(g_wqb, g_xb + (size_t)b * DIM * HW_, b_qkv, nores, noout,
              g_tmpb + (size_t)b * QKV_CH * HW_);
}

__global__ __launch_bounds__(256) void k5_gemm(
    const float* __restrict__ b_proj, const float* __restrict__ x,
    float* __restrict__ out)
{
    const int b = blockIdx.z;
    __nv_bfloat16* no16 = 0;
    gemm_body(g_weffb + (size_t)b * DIM * DIM, g_vb + (size_t)b * DIM * HW_,
              b_proj, x + (size_t)b * DIM * HW_, out + (size_t)b * DIM * HW_, no16);
}

__device__ __forceinline__ float warp_red(float v)
{
    v += __shfl_down_sync(0xffffffffu, v, 16);
    v += __shfl_down_sync(0xffffffffu, v, 8);
    v += __shfl_down_sync(0xffffffffu, v, 4);
    v += __shfl_down_sync(0xffffffffu, v, 2);
    v += __shfl_down_sync(0xffffffffu, v, 1);
    return v;
}

// Fused dwconv(q,k) + Gram/norm partials, 4-way split:
// block = (strip*4 + quad, cc, b); quad = qh*2+kh; 4 q-chans x 4 k-chans.
// smem: 8 planes x 10 rows x pitch 144 bf16.
__global__ __launch_bounds__(256) void k2qk(
    const float* __restrict__ w_dw, const float* __restrict__ b_dw)
{
    const int b = blockIdx.z;
    const int cc = blockIdx.y;
    const int strip = blockIdx.x >> 2;
    const int quad = blockIdx.x & 3;
    const int qh = quad >> 1;
    const int kh = quad & 1;
    const int y0 = strip * 8;

    __shared__ __align__(16) char sqk[23040];
    __shared__ float sw[8][9];
    __shared__ float sbias[8];

    __nv_bfloat16* sm = (__nv_bfloat16*)sqk;
    const __nv_bfloat16* tb = g_tmpb + (size_t)b * QKV_CH * HW_;

    // plane ci: 0..3 -> q chan (qh*4+ci)*48+cc ; 4..7 -> k chan 384+(kh*4+ci-4)*48+cc
    for (int idx = threadIdx.x; idx < 1280; idx += 256) {
        int ch = idx / 160;
        int rem = idx - ch * 160;
        int row = rem >> 4;
        int u = rem & 15;
        int gy = y0 - 1 + row;
        uint4 v;
        v.x = 0u; v.y = 0u; v.z = 0u; v.w = 0u;
        if (gy >= 0 && gy < 128) {
            int chg = (qh * 4 + ch) * 48 + cc;
            if (ch >= 4) chg = 384 + (kh * 4 + ch - 4) * 48 + cc;
            v = *(const uint4*)(tb + (size_t)chg * HW_ + gy * 128 + u * 8);
        }
        *(uint4*)(sm + ((ch * 10 + row) * 144 + 8 + u * 8)) = v;
    }
    for (int idx = threadIdx.x; idx < 160; idx += 256) {
        int ch = idx / 20;
        int rem = idx - ch * 20;
        int row = rem >> 1;
        int col = 7;
        if (rem & 1) col = 136;
        sm[(ch * 10 + row) * 144 + col] = __float2bfloat16(0.f);
    }
    if (threadIdx.x < 72) {
        int ci = threadIdx.x / 9;
        int j = threadIdx.x - ci * 9;
        int chg = (qh * 4 + ci) * 48 + cc;
        if (ci >= 4) chg = 384 + (kh * 4 + ci - 4) * 48 + cc;
        sw[ci][j] = w_dw[chg * 9 + j];
    }
    if (threadIdx.x >= 72 && threadIdx.x < 80) {
        int ci = threadIdx.x - 72;
        int chg = (qh * 4 + ci) * 48 + cc;
        if (ci >= 4) chg = 384 + (kh * 4 + ci - 4) * 48 + cc;
        sbias[ci] = b_dw[chg];
    }
    __syncthreads();

    const int r = threadIdx.x >> 5;
    const int x0 = (threadIdx.x & 31) * 4;

    float acc[4][4];
    float aq[4];
    float ak[4];
    float qo[4][4];
    #pragma unroll
    for (int n = 0; n < 4; n++) {
        aq[n] = 0.f;
        ak[n] = 0.f;
        #pragma unroll
        for (int m = 0; m < 4; m++) acc[n][m] = 0.f;
    }

    #pragma unroll
    for (int n = 0; n < 4; n++) {
        float v0[8];
        float v1[8];
        float v2[8];
        #pragma unroll
        for (int j = 0; j < 4; j++) {
            int base0 = (n * 10 + r) * 144 + 6 + x0 + 2 * j;
            float2 f0 = __bfloat1622float2(*(const __nv_bfloat162*)(sm + base0));
            float2 f1 = __bfloat1622float2(*(const __nv_bfloat162*)(sm + base0 + 144));
            float2 f2 = __bfloat1622float2(*(const __nv_bfloat162*)(sm + base0 + 288));
            v0[2 * j] = f0.x; v0[2 * j + 1] = f0.y;
            v1[2 * j] = f1.x; v1[2 * j + 1] = f1.y;
            v2[2 * j] = f2.x; v2[2 * j + 1] = f2.y;
        }
        float bi = sbias[n];
        #pragma unroll
        for (int i = 0; i < 4; i++) {
            float o = bi;
            o += sw[n][0] * v0[1 + i];
            o += sw[n][1] * v0[2 + i];
            o += sw[n][2] * v0[3 + i];
            o += sw[n][3] * v1[1 + i];
            o += sw[n][4] * v1[2 + i];
            o += sw[n][5] * v1[3 + i];
            o += sw[n][6] * v2[1 + i];
            o += sw[n][7] * v2[2 + i];
            o += sw[n][8] * v2[3 + i];
            qo[n][i] = o;
            aq[n] += o * o;
        }
    }

    #pragma unroll
    for (int m = 0; m < 4; m++) {
        float v0[8];
        float v1[8];
        float v2[8];
        #pragma unroll
        for (int j = 0; j < 4; j++) {
            int base0 = ((4 + m) * 10 + r) * 144 + 6 + x0 + 2 * j;
            float2 f0 = __bfloat1622float2(*(const __nv_bfloat162*)(sm + base0));
            float2 f1 = __bfloat1622float2(*(const __nv_bfloat162*)(sm + base0 + 144));
            float2 f2 = __bfloat1622float2(*(const __nv_bfloat162*)(sm + base0 + 288));
            v0[2 * j] = f0.x; v0[2 * j + 1] = f0.y;
            v1[2 * j] = f1.x; v1[2 * j + 1] = f1.y;
            v2[2 * j] = f2.x; v2[2 * j + 1] = f2.y;
        }
        float bi = sbias[4 + m];
        float ko[4];
        #pragma unroll
        for (int i = 0; i < 4; i++) {
            float o = bi;
            o += sw[4 + m][0] * v0[1 + i];
            o += sw[4 + m][1] * v0[2 + i];
            o += sw[4 + m][2] * v0[3 + i];
            o += sw[4 + m][3] * v1[1 + i];
            o += sw[4 + m][4] * v1[2 + i];
            o += sw[4 + m][5] * v1[3 + i];
            o += sw[4 + m][6] * v2[1 + i];
            o += sw[4 + m][7] * v2[2 + i];
            o += sw[4 + m][8] * v2[3 + i];
            ko[i] = o;
            ak[m] += o * o;
        }
        #pragma unroll
        for (int n = 0; n < 4; n++) {
            #pragma unroll
            for (int i = 0; i < 4; i++) acc[n][m] += qo[n][i] * ko[i];
        }
    }

    __syncthreads();
    // local reduce: 24 values/warp: 0-15 acc, 16-19 aq, 20-23 ak
    float* red = (float*)sqk;
    const int lane = threadIdx.x & 31;
    const int wid = threadIdx.x >> 5;
    #pragma unroll
    for (int n = 0; n < 4; n++) {
        #pragma unroll
        for (int m = 0; m < 4; m++) {
            float s = warp_red(acc[n][m]);
            if (lane == 0) red[wid * 24 + n * 4 + m] = s;
        }
        float s1 = warp_red(aq[n]);
        if (lane == 0) red[wid * 24 + 16 + n] = s1;
        float s2 = warp_red(ak[n]);
        if (lane == 0) red[wid * 24 + 20 + n] = s2;
    }
    __syncthreads();
    if (threadIdx.x < 80) {
        int e = threadIdx.x;
        float t = 0.f;
        int col = -1;
        if (e < 64) {
            int n = e >> 3;
            int m = e & 7;
            if ((n >> 2) == qh && (m >> 2) == kh) col = (n & 3) * 4 + (m & 3);
        } else if (e < 72) {
            int n = e - 64;
            if (kh == 0 && (n >> 2) == qh) col = 16 + (n & 3);
        } else {
            int m = e - 72;
            if (qh == 0 && (m >> 2) == kh) col = 20 + (m & 3);
        }
        if (col >= 0) {
            #pragma unroll
            for (int w = 0; w < 8; w++) t += red[w * 24 + col];
        }
        g_part[((size_t)b * NPART + (size_t)blockIdx.y * 64 + blockIdx.x) * 80 + e] = t;
    }
}

// dwconv for v channels only -> g_vb (bf16)
__global__ __launch_bounds__(256) void k2v(
    const float* __restrict__ w_dw, const float* __restrict__ b_dw)
{
    const int chv = blockIdx.y;
    const int ch = 768 + chv;
    const int b = blockIdx.z;
    const int y0 = blockIdx.x * 16;

    __shared__ __align__(16) __nv_bfloat16 smv[18 * 144];
    const __nv_bfloat16* src = g_tmpb + ((size_t)b * QKV_CH + ch) * HW_;

    for (int idx = threadIdx.x; idx < 288; idx += 256) {
        int row = idx >> 4;
        int u = idx & 15;
        int gy = y0 - 1 + row;
        uint4 v;
        v.x = 0u; v.y = 0u; v.z = 0u; v.w = 0u;
        if (gy >= 0 && gy < 128) v = *(const uint4*)(src + gy * 128 + u * 8);
        *(uint4*)(smv + (row * 144 + 8 + u * 8)) = v;
    }
    if (threadIdx.x < 36) {
        int row = threadIdx.x >> 1;
        int col = 7;
        if (threadIdx.x & 1) col = 136;
        smv[row * 144 + col] = __float2bfloat16(0.f);
    }
    __syncthreads();

    float wv[9];
    #pragma unroll
    for (int i = 0; i < 9; i++) wv[i] = w_dw[ch * 9 + i];
    float bi = b_dw[ch];

    const int r = threadIdx.x >> 4;
    const int x0 = (threadIdx.x & 15) * 8;

    float v0[12];
    float v1[12];
    float v2[12];
    #pragma unroll
    for (int j = 0; j < 6; j++) {
        int base0 = r * 144 + 6 + x0 + 2 * j;
        float2 f0 = __bfloat1622float2(*(const __nv_bfloat162*)(smv + base0));
        float2 f1 = __bfloat1622float2(*(const __nv_bfloat162*)(smv + base0 + 144));
        float2 f2 = __bfloat1622float2(*(const __nv_bfloat162*)(smv + base0 + 288));
        v0[2 * j] = f0.x; v0[2 * j + 1] = f0.y;
        v1[2 * j] = f1.x; v1[2 * j + 1] = f1.y;
        v2[2 * j] = f2.x; v2[2 * j + 1] = f2.y;
    }

    float o[8];
    #pragma unroll
    for (int i = 0; i < 8; i++) {
        float t = bi;
        t += wv[0] * v0[1 + i];
        t += wv[1] * v0[2 + i];
        t += wv[2] * v0[3 + i];
        t += wv[3] * v1[1 + i];
        t += wv[4] * v1[2 + i];
        t += wv[5] * v1[3 + i];
        t += wv[6] * v2[1 + i];
        t += wv[7] * v2[2 + i];
        t += wv[8] * v2[3 + i];
        o[i] = t;
    }

    const int p = (y0 + r) * 128 + x0;
    __nv_bfloat162* dst = (__nv_bfloat162*)(g_vb + ((size_t)b * DIM + chv) * HW_ + p);
    dst[0] = __floats2bfloat162_rn(o[0], o[1]);
    dst[1] = __floats2bfloat162_rn(o[2], o[3]);
    dst[2] = __floats2bfloat162_rn(o[4], o[5]);
    dst[3] = __floats2bfloat162_rn(o[6], o[7]);
}

__global__ __launch_bounds__(640) void k4a_softmax(const float* __restrict__ temperature)
{
    const int b = blockIdx.x;
    __shared__ float red[80];

    const int e = threadIdx.x >> 3;
    const int j = threadIdx.x & 7;
    float t = 0.f;
    for (int s = j; s < NPART; s += 8)
        t += g_part[((size_t)b * NPART + s) * 80 + e];
    t += __shfl_down_sync(0xffffffffu, t, 4);
    t += __shfl_down_sync(0xffffffffu, t, 2);
    t += __shfl_down_sync(0xffffffffu, t, 1);
    if (j == 0) red[e] = t;
    __syncthreads();

    if (threadIdx.x < 8) {
        const int n = threadIdx.x;
        const float temp = temperature[0];
        float qn = fmaxf(sqrtf(red[64 + n]), 1e-12f);
        float logit[8];
        float mx = -1e30f;
        #pragma unroll
        for (int m = 0; m < 8; m++) {
            float kn = fmaxf(sqrtf(red[72 + m]), 1e-12f);
            float l = temp * red[n * 8 + m] / (qn * kn);
            logit[m] = l;
            mx = fmaxf(mx, l);
        }
        float sum = 0.f;
        float ex[8];
        #pragma unroll
        for (int m = 0; m < 8; m++) {
            ex[m] = expf(logit[m] - mx);
            sum += ex[m];
        }
        float inv = 1.f / sum;
        #pragma unroll
        for (int m = 0; m < 8; m++) g_attn[b * 64 + n * 8 + m] = ex[m] * inv;
    }
}

__global__ __launch_bounds__(256) void k4b_weff(const float* __restrict__ w_proj)
{
    const int b = blockIdx.y;
    __shared__ float at[64];
    if (threadIdx.x < 64) at[threadIdx.x] = g_attn[b * 64 + threadIdx.x];
    __syncthreads();

    const int idx = blockIdx.x * 256 + threadIdx.x;
    const int co = idx / DIM;
    const int jj = idx % DIM;
    const int m = jj / CC_;
    const int cc = jj % CC_;
    float s = 0.f;
    #pragma unroll
    for (int n = 0; n < 8; n++)
        s += at[n * 8 + m] * __ldg(&w_proj[co * DIM + n * CC_ + cc]);
    g_weffb[(size_t)b * DIM * DIM + idx] = __float2bfloat16(s);
}

extern "C" void kernel_launch(void* const* d_in, const int* in_sizes, int n_in,
                              void* d_out, int out_size)
{
    const float* x = (const float*)d_in[0];
    const float* temp = (const float*)d_in[1];
    const float* w_qkv = (const float*)d_in[2];
    const float* b_qkv = (const float*)d_in[3];
    const float* w_dw = (const float*)d_in[4];
    const float* b_dw = (const float*)d_in[5];
    const float* w_proj = (const float*)d_in[6];
    const float* b_proj = (const float*)d_in[7];
    float* out = (float*)d_out;

    int gcx = 24576;
    int gcw = 432;
    dim3 g1(128, 9, 4);
    dim3 gqk(64, 48, 4);
    dim3 gv(8, 384, 4);
    dim3 g4b(576, 4);
    dim3 g5(128, 3, 4);
    int nb4 = 4;

    kc_conv_x<<<gcx, 256>>>(x);
    kc_conv_w<<<gcw, 256>>>(w_qkv);
    k1_gemm<<<g1, 256>>>(b_qkv);
    k2qk<<<gqk, 256>>>(w_dw, b_dw);
    k2v<<<gv, 256>>>(w_dw, b_dw);
    k4a_softmax<<<nb4, 640>>>(temp);
    k4b_weff<<<g4b, 256>>>(w_proj);
    k5_gemm<<<g5, 256>>>(b_proj, x, out);
}

// round 14
// speedup vs baseline: 1.1228x; 1.0055x over previous
#include <cuda_runtime.h>
#include <cuda_bf16.h>
#include <cuda_pipeline.h>
#include <mma.h>
#include <math.h>

#define BB 4
#define DIM 384
#define QKV_CH 1152
#define HW_ 16384
#define CC_ 48
#define NPART 768

namespace wx = nvcuda::wmma;

static __device__ __nv_bfloat16 g_tmpb[(size_t)BB * QKV_CH * HW_];
static __device__ __nv_bfloat16 g_vb[(size_t)BB * DIM * HW_];
static __device__ __nv_bfloat16 g_xb[(size_t)BB * DIM * HW_];
static __device__ __nv_bfloat16 g_wqb[(size_t)QKV_CH * DIM];
static __device__ float g_part[(size_t)BB * NPART * 80];
static __device__ float g_attn[BB * 64];
static __device__ __nv_bfloat16 g_weffb[(size_t)BB * DIM * DIM];

__global__ __launch_bounds__(256) void kc_conv_x(const float* __restrict__ src)
{
    int i = blockIdx.x * 256 + threadIdx.x;
    float4 v = ((const float4*)src)[i];
    ((__nv_bfloat162*)g_xb)[2 * i] = __floats2bfloat162_rn(v.x, v.y);
    ((__nv_bfloat162*)g_xb)[2 * i + 1] = __floats2bfloat162_rn(v.z, v.w);
}

__global__ __launch_bounds__(256) void kc_conv_w(const float* __restrict__ src)
{
    int i = blockIdx.x * 256 + threadIdx.x;
    float4 v = ((const float4*)src)[i];
    ((__nv_bfloat162*)g_wqb)[2 * i] = __floats2bfloat162_rn(v.x, v.y);
    ((__nv_bfloat162*)g_wqb)[2 * i + 1] = __floats2bfloat162_rn(v.z, v.w);
}

// R7 GEMM body (proven best): 2-stage cp.async, 128x128 tile, 256 thr, static smem.
__device__ __forceinline__ void gemm_body(
    const __nv_bfloat16* __restrict__ Ab,
    const __nv_bfloat16* __restrict__ Bb,
    const float* __restrict__ bias,
    const float* __restrict__ rbase,
    float* __restrict__ ob,
    __nv_bfloat16* __restrict__ ob16)
{
    __shared__ __align__(16) char sbuf[37888];

    const int row0 = blockIdx.y * 128;
    const int col0 = blockIdx.x * 128;

    const int tid = threadIdx.x;
    const int lane = tid & 31;
    const int wid = tid >> 5;
    const int wm = wid & 1;
    const int wn = wid >> 1;

    const int ar = tid >> 2;
    const int acol = (tid & 3) * 8;
    const int br = tid >> 4;
    const int bcol = (tid & 15) * 8;

    char* a_dst0 = sbuf + ar * 80 + acol * 2;
    char* a_dst1 = sbuf + (ar + 64) * 80 + acol * 2;
    char* b_dst0 = sbuf + 10240 + br * 272 + bcol * 2;
    char* b_dst1 = sbuf + 10240 + (br + 16) * 272 + bcol * 2;

    wx::fragment<wx::accumulator, 16, 16, 16, float> c[4][2];
    for (int i = 0; i < 4; i++)
        for (int j = 0; j < 2; j++)
            wx::fill_fragment(c[i][j], 0.0f);

    const __nv_bfloat16* a_src0 = Ab + (size_t)(row0 + ar) * DIM + acol;
    const __nv_bfloat16* a_src1 = a_src0 + (size_t)64 * DIM;
    const __nv_bfloat16* b_src0 = Bb + (size_t)br * HW_ + col0 + bcol;
    const __nv_bfloat16* b_src1 = b_src0 + (size_t)16 * HW_;

    __pipeline_memcpy_async(a_dst0, a_src0, 16);
    __pipeline_memcpy_async(a_dst1, a_src1, 16);
    __pipeline_memcpy_async(b_dst0, b_src0, 16);
    __pipeline_memcpy_async(b_dst1, b_src1, 16);
    __pipeline_commit();

    for (int kt = 0; kt < 12; kt++) {
        if (kt < 11) {
            int nb = (kt + 1) & 1;
            int koff = (kt + 1) * 32;
            __pipeline_memcpy_async(a_dst0 + nb * 18944, a_src0 + koff, 16);
            __pipeline_memcpy_async(a_dst1 + nb * 18944, a_src1 + koff, 16);
            __pipeline_memcpy_async(b_dst0 + nb * 18944, b_src0 + (size_t)koff * HW_, 16);
            __pipeline_memcpy_async(b_dst1 + nb * 18944, b_src1 + (size_t)koff * HW_, 16);
            __pipeline_commit();
            __pipeline_wait_prior(1);
        } else {
            __pipeline_wait_prior(0);
        }
        __syncthreads();

        const __nv_bfloat16* As = (const __nv_bfloat16*)(sbuf + (kt & 1) * 18944);
        const __nv_bfloat16* Bs = (const __nv_bfloat16*)(sbuf + (kt & 1) * 18944 + 10240);

        for (int ks = 0; ks < 2; ks++) {
            wx::fragment<wx::matrix_a, 16, 16, 16, __nv_bfloat16, wx::row_major> a[4];
            wx::fragment<wx::matrix_b, 16, 16, 16, __nv_bfloat16, wx::row_major> bf[2];
            for (int i = 0; i < 4; i++)
                wx::load_matrix_sync(a[i], As + (wm * 64 + i * 16) * 40 + ks * 16, 40);
            for (int j = 0; j < 2; j++)
                wx::load_matrix_sync(bf[j], Bs + (ks * 16) * 136 + wn * 32 + j * 16, 136);
            for (int i = 0; i < 4; i++)
                for (int j = 0; j < 2; j++)
                    wx::mma_sync(c[i][j], a[i], bf[j], c[i][j]);
        }
        __syncthreads();
    }

    float* Csw = (float*)sbuf + wid * 512;

    for (int i = 0; i < 4; i++) {
        wx::store_matrix_sync(Csw, c[i][0], 32, wx::mem_row_major);
        wx::store_matrix_sync(Csw + 16, c[i][1], 32, wx::mem_row_major);
        __syncwarp();
        int r = lane >> 1;
        int cb = (lane & 1) * 16;
        int gr = row0 + wm * 64 + i * 16 + r;
        int gc = col0 + wn * 32 + cb;
        float bi = bias[gr];
        for (int q = 0; q < 16; q += 4) {
            float4 v;
            v.x = Csw[r * 32 + cb + q] + bi;
            v.y = Csw[r * 32 + cb + q + 1] + bi;
            v.z = Csw[r * 32 + cb + q + 2] + bi;
            v.w = Csw[r * 32 + cb + q + 3] + bi;
            if (ob16) {
                __nv_bfloat162* op16 = (__nv_bfloat162*)(ob16 + (size_t)gr * HW_ + gc);
                op16[(q >> 1)] = __floats2bfloat162_rn(v.x, v.y);
                op16[(q >> 1) + 1] = __floats2bfloat162_rn(v.z, v.w);
            } else {
                if (rbase) {
                    const float* rp = rbase + (size_t)gr * HW_ + gc + q;
                    float4 xv = *(const float4*)(rp);
                    v.x += xv.x;
                    v.y += xv.y;
                    v.z += xv.z;
                    v.w += xv.w;
                }
                *(float4*)(ob + (size_t)gr * HW_ + gc + q) = v;
            }
        }
        __syncwarp();
    }
}

__global__ __launch_bounds__(256) void k1_gemm(const float* __restrict__ b_qkv)
{
    const int b = blockIdx.z;
    const float* nores = 0;
    float* noout = 0;
    gemm_body(g_wqb, g_xb + (size_t)b * DIM * HW_, b_qkv, nores, noout,
              g_tmpb + (size_t)b * QKV_CH * HW_);
}

__global__ __launch_bounds__(256) void k5_gemm(
    const float* __restrict__ b_proj, const float* __restrict__ x,
    float* __restrict__ out)
{
    const int b = blockIdx.z;
    __nv_bfloat16* no16 = 0;
    gemm_body(g_weffb + (size_t)b * DIM * DIM, g_vb + (size_t)b * DIM * HW_,
              b_proj, x + (size_t)b * DIM * HW_, out + (size_t)b * DIM * HW_, no16);
}

__device__ __forceinline__ float warp_red(float v)
{
    v += __shfl_down_sync(0xffffffffu, v, 16);
    v += __shfl_down_sync(0xffffffffu, v, 8);
    v += __shfl_down_sync(0xffffffffu, v, 4);
    v += __shfl_down_sync(0xffffffffu, v, 2);
    v += __shfl_down_sync(0xffffffffu, v, 1);
    return v;
}

// Fused kernel: blockIdx.x < 768 -> dwconv(q,k)+Gram partials (R7 form);
// blockIdx.x >= 768 -> dwconv(v) -> g_vb. Independent jobs co-scheduled.
__global__ __launch_bounds__(256) void k2_fused(
    const float* __restrict__ w_dw, const float* __restrict__ b_dw)
{
    __shared__ __align__(16) char sqk[46080];
    __shared__ float sw[16][9];
    __shared__ float sbias[16];

    const int b = blockIdx.z;

    if (blockIdx.x < 768) {
        const int cc = blockIdx.x >> 4;
        const int strip = blockIdx.x & 15;
        const int y0 = strip * 8;

        __nv_bfloat16* sm = (__nv_bfloat16*)sqk;
        const __nv_bfloat16* tb = g_tmpb + (size_t)b * QKV_CH * HW_;

        for (int idx = threadIdx.x; idx < 2560; idx += 256) {
            int ch = idx / 160;
            int rem = idx - ch * 160;
            int row = rem >> 4;
            int u = rem & 15;
            int gy = y0 - 1 + row;
            uint4 v;
            v.x = 0u; v.y = 0u; v.z = 0u; v.w = 0u;
            if (gy >= 0 && gy < 128) {
                int chg = ch * 48 + cc;
                if (ch >= 8) chg = 384 + (ch - 8) * 48 + cc;
                v = *(const uint4*)(tb + (size_t)chg * HW_ + gy * 128 + u * 8);
            }
            *(uint4*)(sm + ((ch * 10 + row) * 144 + 8 + u * 8)) = v;
        }
        for (int idx = threadIdx.x; idx < 320; idx += 256) {
            int ch = idx / 20;
            int rem = idx - ch * 20;
            int row = rem >> 1;
            int col = 7;
            if (rem & 1) col = 136;
            sm[(ch * 10 + row) * 144 + col] = __float2bfloat16(0.f);
        }
        if (threadIdx.x < 144) {
            int ci = threadIdx.x / 9;
            int j = threadIdx.x - ci * 9;
            int chg = ci * 48 + cc;
            if (ci >= 8) chg = 384 + (ci - 8) * 48 + cc;
            sw[ci][j] = w_dw[chg * 9 + j];
        }
        if (threadIdx.x >= 144 && threadIdx.x < 160) {
            int ci = threadIdx.x - 144;
            int chg = ci * 48 + cc;
            if (ci >= 8) chg = 384 + (ci - 8) * 48 + cc;
            sbias[ci] = b_dw[chg];
        }
        __syncthreads();

        const int r = threadIdx.x >> 5;
        const int x0 = (threadIdx.x & 31) * 4;

        float acc[8][8];
        float aq[8];
        float ak[8];
        float qo[8][4];
        #pragma unroll
        for (int n = 0; n < 8; n++) {
            aq[n] = 0.f;
            ak[n] = 0.f;
            #pragma unroll
            for (int m = 0; m < 8; m++) acc[n][m] = 0.f;
        }

        #pragma unroll
        for (int n = 0; n < 8; n++) {
            float v0[8];
            float v1[8];
            float v2[8];
            #pragma unroll
            for (int j = 0; j < 4; j++) {
                int base0 = (n * 10 + r) * 144 + 6 + x0 + 2 * j;
                float2 f0 = __bfloat1622float2(*(const __nv_bfloat162*)(sm + base0));
                float2 f1 = __bfloat1622float2(*(const __nv_bfloat162*)(sm + base0 + 144));
                float2 f2 = __bfloat1622float2(*(const __nv_bfloat162*)(sm + base0 + 288));
                v0[2 * j] = f0.x; v0[2 * j + 1] = f0.y;
                v1[2 * j] = f1.x; v1[2 * j + 1] = f1.y;
                v2[2 * j] = f2.x; v2[2 * j + 1] = f2.y;
            }
            float bi = sbias[n];
            #pragma unroll
            for (int i = 0; i < 4; i++) {
                float o = bi;
                o += sw[n][0] * v0[1 + i];
                o += sw[n][1] * v0[2 + i];
                o += sw[n][2] * v0[3 + i];
                o += sw[n][3] * v1[1 + i];
                o += sw[n][4] * v1[2 + i];
                o += sw[n][5] * v1[3 + i];
                o += sw[n][6] * v2[1 + i];
                o += sw[n][7] * v2[2 + i];
                o += sw[n][8] * v2[3 + i];
                qo[n][i] = o;
                aq[n] += o * o;
            }
        }

        #pragma unroll
        for (int m = 0; m < 8; m++) {
            float v0[8];
            float v1[8];
            float v2[8];
            #pragma unroll
            for (int j = 0; j < 4; j++) {
                int base0 = ((8 + m) * 10 + r) * 144 + 6 + x0 + 2 * j;
                float2 f0 = __bfloat1622float2(*(const __nv_bfloat162*)(sm + base0));
                float2 f1 = __bfloat1622float2(*(const __nv_bfloat162*)(sm + base0 + 144));
                float2 f2 = __bfloat1622float2(*(const __nv_bfloat162*)(sm + base0 + 288));
                v0[2 * j] = f0.x; v0[2 * j + 1] = f0.y;
                v1[2 * j] = f1.x; v1[2 * j + 1] = f1.y;
                v2[2 * j] = f2.x; v2[2 * j + 1] = f2.y;
            }
            float bi = sbias[8 + m];
            float ko[4];
            #pragma unroll
            for (int i = 0; i < 4; i++) {
                float o = bi;
                o += sw[8 + m][0] * v0[1 + i];
                o += sw[8 + m][1] * v0[2 + i];
                o += sw[8 + m][2] * v0[3 + i];
                o += sw[8 + m][3] * v1[1 + i];
                o += sw[8 + m][4] * v1[2 + i];
                o += sw[8 + m][5] * v1[3 + i];
                o += sw[8 + m][6] * v2[1 + i];
                o += sw[8 + m][7] * v2[2 + i];
                o += sw[8 + m][8] * v2[3 + i];
                ko[i] = o;
                ak[m] += o * o;
            }
            #pragma unroll
            for (int n = 0; n < 8; n++) {
                #pragma unroll
                for (int i = 0; i < 4; i++) acc[n][m] += qo[n][i] * ko[i];
            }
        }

        __syncthreads();
        float* red = (float*)sqk;
        const int lane = threadIdx.x & 31;
        const int wid = threadIdx.x >> 5;
        #pragma unroll
        for (int n = 0; n < 8; n++) {
            #pragma unroll
            for (int m = 0; m < 8; m++) {
                float s = warp_red(acc[n][m]);
                if (lane == 0) red[wid * 80 + n * 8 + m] = s;
            }
            float s1 = warp_red(aq[n]);
            if (lane == 0) red[wid * 80 + 64 + n] = s1;
            float s2 = warp_red(ak[n]);
            if (lane == 0) red[wid * 80 + 72 + n] = s2;
        }
        __syncthreads();
        if (threadIdx.x < 80) {
            float t = 0.f;
            #pragma unroll
            for (int w = 0; w < 8; w++) t += red[w * 80 + threadIdx.x];
            g_part[((size_t)b * NPART + cc * 16 + strip) * 80 + threadIdx.x] = t;
        }
    } else {
        const int j = blockIdx.x - 768;
        const int chv = j >> 3;
        const int ch = 768 + chv;
        const int y0 = (j & 7) * 16;

        __nv_bfloat16* smv = (__nv_bfloat16*)sqk;
        const __nv_bfloat16* src = g_tmpb + ((size_t)b * QKV_CH + ch) * HW_;

        for (int idx = threadIdx.x; idx < 288; idx += 256) {
            int row = idx >> 4;
            int u = idx & 15;
            int gy = y0 - 1 + row;
            uint4 v;
            v.x = 0u; v.y = 0u; v.z = 0u; v.w = 0u;
            if (gy >= 0 && gy < 128) v = *(const uint4*)(src + gy * 128 + u * 8);
            *(uint4*)(smv + (row * 144 + 8 + u * 8)) = v;
        }
        if (threadIdx.x < 36) {
            int row = threadIdx.x >> 1;
            int col = 7;
            if (threadIdx.x & 1) col = 136;
            smv[row * 144 + col] = __float2bfloat16(0.f);
        }
        __syncthreads();

        float wv[9];
        #pragma unroll
        for (int i = 0; i < 9; i++) wv[i] = w_dw[ch * 9 + i];
        float bi = b_dw[ch];

        const int r = threadIdx.x >> 4;
        const int x0 = (threadIdx.x & 15) * 8;

        float v0[12];
        float v1[12];
        float v2[12];
        #pragma unroll
        for (int jj = 0; jj < 6; jj++) {
            int base0 = r * 144 + 6 + x0 + 2 * jj;
            float2 f0 = __bfloat1622float2(*(const __nv_bfloat162*)(smv + base0));
            float2 f1 = __bfloat1622float2(*(const __nv_bfloat162*)(smv + base0 + 144));
            float2 f2 = __bfloat1622float2(*(const __nv_bfloat162*)(smv + base0 + 288));
            v0[2 * jj] = f0.x; v0[2 * jj + 1] = f0.y;
            v1[2 * jj] = f1.x; v1[2 * jj + 1] = f1.y;
            v2[2 * jj] = f2.x; v2[2 * jj + 1] = f2.y;
        }

        float o[8];
        #pragma unroll
        for (int i = 0; i < 8; i++) {
            float t = bi;
            t += wv[0] * v0[1 + i];
            t += wv[1] * v0[2 + i];
            t += wv[2] * v0[3 + i];
            t += wv[3] * v1[1 + i];
            t += wv[4] * v1[2 + i];
            t += wv[5] * v1[3 + i];
            t += wv[6] * v2[1 + i];
            t += wv[7] * v2[2 + i];
            t += wv[8] * v2[3 + i];
            o[i] = t;
        }

        const int p = (y0 + r) * 128 + x0;
        __nv_bfloat162* dst = (__nv_bfloat162*)(g_vb + ((size_t)b * DIM + chv) * HW_ + p);
        dst[0] = __floats2bfloat162_rn(o[0], o[1]);
        dst[1] = __floats2bfloat162_rn(o[2], o[3]);
        dst[2] = __floats2bfloat162_rn(o[4], o[5]);
        dst[3] = __floats2bfloat162_rn(o[6], o[7]);
    }
}

__global__ __launch_bounds__(640) void k4a_softmax(const float* __restrict__ temperature)
{
    const int b = blockIdx.x;
    __shared__ float red[80];

    const int e = threadIdx.x >> 3;
    const int j = threadIdx.x & 7;
    float t = 0.f;
    for (int s = j; s < NPART; s += 8)
        t += g_part[((size_t)b * NPART + s) * 80 + e];
    t += __shfl_down_sync(0xffffffffu, t, 4);
    t += __shfl_down_sync(0xffffffffu, t, 2);
    t += __shfl_down_sync(0xffffffffu, t, 1);
    if (j == 0) red[e] = t;
    __syncthreads();

    if (threadIdx.x < 8) {
        const int n = threadIdx.x;
        const float temp = temperature[0];
        float qn = fmaxf(sqrtf(red[64 + n]), 1e-12f);
        float logit[8];
        float mx = -1e30f;
        #pragma unroll
        for (int m = 0; m < 8; m++) {
            float kn = fmaxf(sqrtf(red[72 + m]), 1e-12f);
            float l = temp * red[n * 8 + m] / (qn * kn);
            logit[m] = l;
            mx = fmaxf(mx, l);
        }
        float sum = 0.f;
        float ex[8];
        #pragma unroll
        for (int m = 0; m < 8; m++) {
            ex[m] = expf(logit[m] - mx);
            sum += ex[m];
        }
        float inv = 1.f / sum;
        #pragma unroll
        for (int m = 0; m < 8; m++) g_attn[b * 64 + n * 8 + m] = ex[m] * inv;
    }
}

__global__ __launch_bounds__(256) void k4b_weff(const float* __restrict__ w_proj)
{
    const int b = blockIdx.y;
    __shared__ float at[64];
    if (threadIdx.x < 64) at[threadIdx.x] = g_attn[b * 64 + threadIdx.x];
    __syncthreads();

    const int idx = blockIdx.x * 256 + threadIdx.x;
    const int co = idx / DIM;
    const int jj = idx % DIM;
    const int m = jj / CC_;
    const int cc = jj % CC_;
    float s = 0.f;
    #pragma unroll
    for (int n = 0; n < 8; n++)
        s += at[n * 8 + m] * __ldg(&w_proj[co * DIM + n * CC_ + cc]);
    g_weffb[(size_t)b * DIM * DIM + idx] = __float2bfloat16(s);
}

extern "C" void kernel_launch(void* const* d_in, const int* in_sizes, int n_in,
                              void* d_out, int out_size)
{
    const float* x = (const float*)d_in[0];
    const float* temp = (const float*)d_in[1];
    const float* w_qkv = (const float*)d_in[2];
    const float* b_qkv = (const float*)d_in[3];
    const float* w_dw = (const float*)d_in[4];
    const float* b_dw = (const float*)d_in[5];
    const float* w_proj = (const float*)d_in[6];
    const float* b_proj = (const float*)d_in[7];
    float* out = (float*)d_out;

    int gcx = 24576;
    int gcw = 432;
    dim3 g1(128, 9, 4);
    dim3 g2(3840, 1, 4);
    dim3 g4b(576, 4);
    dim3 g5(128, 3, 4);
    int nb4 = 4;

    kc_conv_x<<<gcx, 256>>>(x);
    kc_conv_w<<<gcw, 256>>>(w_qkv);
    k1_gemm<<<g1, 256>>>(b_qkv);
    k2_fused<<<g2, 256>>>(w_dw, b_dw);
    k4a_softmax<<<nb4, 640>>>(temp);
    k4b_weff<<<g4b, 256>>>(w_proj);
    k5_gemm<<<g5, 256>>>(b_proj, x, out);
}

// round 15
// speedup vs baseline: 1.2326x; 1.0978x over previous
#include <cuda_runtime.h>
#include <cuda_bf16.h>
#include <cuda_pipeline.h>
#include <mma.h>
#include <math.h>

#define BB 4
#define DIM 384
#define QKV_CH 1152
#define HW_ 16384
#define CC_ 48
#define NPART 768

namespace wx = nvcuda::wmma;

static __device__ __nv_bfloat16 g_tmpb[(size_t)BB * QKV_CH * HW_];
static __device__ __nv_bfloat16 g_vb[(size_t)BB * DIM * HW_];
static __device__ __nv_bfloat16 g_xb[(size_t)BB * DIM * HW_];
static __device__ __nv_bfloat16 g_wqb[(size_t)QKV_CH * DIM];
static __device__ float g_part[(size_t)BB * NPART * 80];
static __device__ float g_attn[BB * 64];
static __device__ __nv_bfloat16 g_weffb[(size_t)BB * DIM * DIM];

__global__ __launch_bounds__(256) void kc_conv_x(const float* __restrict__ src)
{
    int i = blockIdx.x * 256 + threadIdx.x;
    float4 v = ((const float4*)src)[i];
    ((__nv_bfloat162*)g_xb)[2 * i] = __floats2bfloat162_rn(v.x, v.y);
    ((__nv_bfloat162*)g_xb)[2 * i + 1] = __floats2bfloat162_rn(v.z, v.w);
}

__global__ __launch_bounds__(256) void kc_conv_w(const float* __restrict__ src)
{
    int i = blockIdx.x * 256 + threadIdx.x;
    float4 v = ((const float4*)src)[i];
    ((__nv_bfloat162*)g_wqb)[2 * i] = __floats2bfloat162_rn(v.x, v.y);
    ((__nv_bfloat162*)g_wqb)[2 * i + 1] = __floats2bfloat162_rn(v.z, v.w);
}

// R7 GEMM body (proven best): 2-stage cp.async, 128x128 tile, 256 thr, static smem.
__device__ __forceinline__ void gemm_body(
    const __nv_bfloat16* __restrict__ Ab,
    const __nv_bfloat16* __restrict__ Bb,
    const float* __restrict__ bias,
    const float* __restrict__ rbase,
    float* __restrict__ ob,
    __nv_bfloat16* __restrict__ ob16)
{
    __shared__ __align__(16) char sbuf[37888];

    const int row0 = blockIdx.y * 128;
    const int col0 = blockIdx.x * 128;

    const int tid = threadIdx.x;
    const int lane = tid & 31;
    const int wid = tid >> 5;
    const int wm = wid & 1;
    const int wn = wid >> 1;

    const int ar = tid >> 2;
    const int acol = (tid & 3) * 8;
    const int br = tid >> 4;
    const int bcol = (tid & 15) * 8;

    char* a_dst0 = sbuf + ar * 80 + acol * 2;
    char* a_dst1 = sbuf + (ar + 64) * 80 + acol * 2;
    char* b_dst0 = sbuf + 10240 + br * 272 + bcol * 2;
    char* b_dst1 = sbuf + 10240 + (br + 16) * 272 + bcol * 2;

    wx::fragment<wx::accumulator, 16, 16, 16, float> c[4][2];
    for (int i = 0; i < 4; i++)
        for (int j = 0; j < 2; j++)
            wx::fill_fragment(c[i][j], 0.0f);

    const __nv_bfloat16* a_src0 = Ab + (size_t)(row0 + ar) * DIM + acol;
    const __nv_bfloat16* a_src1 = a_src0 + (size_t)64 * DIM;
    const __nv_bfloat16* b_src0 = Bb + (size_t)br * HW_ + col0 + bcol;
    const __nv_bfloat16* b_src1 = b_src0 + (size_t)16 * HW_;

    __pipeline_memcpy_async(a_dst0, a_src0, 16);
    __pipeline_memcpy_async(a_dst1, a_src1, 16);
    __pipeline_memcpy_async(b_dst0, b_src0, 16);
    __pipeline_memcpy_async(b_dst1, b_src1, 16);
    __pipeline_commit();

    for (int kt = 0; kt < 12; kt++) {
        if (kt < 11) {
            int nb = (kt + 1) & 1;
            int koff = (kt + 1) * 32;
            __pipeline_memcpy_async(a_dst0 + nb * 18944, a_src0 + koff, 16);
            __pipeline_memcpy_async(a_dst1 + nb * 18944, a_src1 + koff, 16);
            __pipeline_memcpy_async(b_dst0 + nb * 18944, b_src0 + (size_t)koff * HW_, 16);
            __pipeline_memcpy_async(b_dst1 + nb * 18944, b_src1 + (size_t)koff * HW_, 16);
            __pipeline_commit();
            __pipeline_wait_prior(1);
        } else {
            __pipeline_wait_prior(0);
        }
        __syncthreads();

        const __nv_bfloat16* As = (const __nv_bfloat16*)(sbuf + (kt & 1) * 18944);
        const __nv_bfloat16* Bs = (const __nv_bfloat16*)(sbuf + (kt & 1) * 18944 + 10240);

        for (int ks = 0; ks < 2; ks++) {
            wx::fragment<wx::matrix_a, 16, 16, 16, __nv_bfloat16, wx::row_major> a[4];
            wx::fragment<wx::matrix_b, 16, 16, 16, __nv_bfloat16, wx::row_major> bf[2];
            for (int i = 0; i < 4; i++)
                wx::load_matrix_sync(a[i], As + (wm * 64 + i * 16) * 40 + ks * 16, 40);
            for (int j = 0; j < 2; j++)
                wx::load_matrix_sync(bf[j], Bs + (ks * 16) * 136 + wn * 32 + j * 16, 136);
            for (int i = 0; i < 4; i++)
                for (int j = 0; j < 2; j++)
                    wx::mma_sync(c[i][j], a[i], bf[j], c[i][j]);
        }
        __syncthreads();
    }

    float* Csw = (float*)sbuf + wid * 512;

    for (int i = 0; i < 4; i++) {
        wx::store_matrix_sync(Csw, c[i][0], 32, wx::mem_row_major);
        wx::store_matrix_sync(Csw + 16, c[i][1], 32, wx::mem_row_major);
        __syncwarp();
        int r = lane >> 1;
        int cb = (lane & 1) * 16;
        int gr = row0 + wm * 64 + i * 16 + r;
        int gc = col0 + wn * 32 + cb;
        float bi = bias[gr];
        for (int q = 0; q < 16; q += 4) {
            float4 v;
            v.x = Csw[r * 32 + cb + q] + bi;
            v.y = Csw[r * 32 + cb + q + 1] + bi;
            v.z = Csw[r * 32 + cb + q + 2] + bi;
            v.w = Csw[r * 32 + cb + q + 3] + bi;
            if (ob16) {
                __nv_bfloat162* op16 = (__nv_bfloat162*)(ob16 + (size_t)gr * HW_ + gc);
                op16[(q >> 1)] = __floats2bfloat162_rn(v.x, v.y);
                op16[(q >> 1) + 1] = __floats2bfloat162_rn(v.z, v.w);
            } else {
                if (rbase) {
                    const float* rp = rbase + (size_t)gr * HW_ + gc + q;
                    float4 xv = *(const float4*)(rp);
                    v.x += xv.x;
                    v.y += xv.y;
                    v.z += xv.z;
                    v.w += xv.w;
                }
                *(float4*)(ob + (size_t)gr * HW_ + gc + q) = v;
            }
        }
        __syncwarp();
    }
}

__global__ __launch_bounds__(256) void k1_gemm(const float* __restrict__ b_qkv)
{
    const int b = blockIdx.z;
    const float* nores = 0;
    float* noout = 0;
    gemm_body(g_wqb, g_xb + (size_t)b * DIM * HW_, b_qkv, nores, noout,
              g_tmpb + (size_t)b * QKV_CH * HW_);
}

__global__ __launch_bounds__(256) void k5_gemm(
    const float* __restrict__ b_proj, const float* __restrict__ x,
    float* __restrict__ out)
{
    const int b = blockIdx.z;
    __nv_bfloat16* no16 = 0;
    gemm_body(g_weffb + (size_t)b * DIM * DIM, g_vb + (size_t)b * DIM * HW_,
              b_proj, x + (size_t)b * DIM * HW_, out + (size_t)b * DIM * HW_, no16);
}

__device__ __forceinline__ float warp_red(float v)
{
    v += __shfl_down_sync(0xffffffffu, v, 16);
    v += __shfl_down_sync(0xffffffffu, v, 8);
    v += __shfl_down_sync(0xffffffffu, v, 4);
    v += __shfl_down_sync(0xffffffffu, v, 2);
    v += __shfl_down_sync(0xffffffffu, v, 1);
    return v;
}

// Fused dwconv(q,k) + Gram/norm partials (R7 tiling) with INLINE per-m warp
// reduction: no persistent acc[8][8] (64 regs saved) -> higher occupancy.
__global__ __launch_bounds__(256) void k2qk(
    const float* __restrict__ w_dw, const float* __restrict__ b_dw)
{
    const int b = blockIdx.z;
    const int cc = blockIdx.y;
    const int strip = blockIdx.x;
    const int y0 = strip * 8;

    __shared__ __align__(16) char sqk[46080];
    __shared__ float sw[16][9];
    __shared__ float sbias[16];

    __nv_bfloat16* sm = (__nv_bfloat16*)sqk;
    const __nv_bfloat16* tb = g_tmpb + (size_t)b * QKV_CH * HW_;

    for (int idx = threadIdx.x; idx < 2560; idx += 256) {
        int ch = idx / 160;
        int rem = idx - ch * 160;
        int row = rem >> 4;
        int u = rem & 15;
        int gy = y0 - 1 + row;
        uint4 v;
        v.x = 0u; v.y = 0u; v.z = 0u; v.w = 0u;
        if (gy >= 0 && gy < 128) {
            int chg = ch * 48 + cc;
            if (ch >= 8) chg = 384 + (ch - 8) * 48 + cc;
            v = *(const uint4*)(tb + (size_t)chg * HW_ + gy * 128 + u * 8);
        }
        *(uint4*)(sm + ((ch * 10 + row) * 144 + 8 + u * 8)) = v;
    }
    for (int idx = threadIdx.x; idx < 320; idx += 256) {
        int ch = idx / 20;
        int rem = idx - ch * 20;
        int row = rem >> 1;
        int col = 7;
        if (rem & 1) col = 136;
        sm[(ch * 10 + row) * 144 + col] = __float2bfloat16(0.f);
    }
    if (threadIdx.x < 144) {
        int ci = threadIdx.x / 9;
        int j = threadIdx.x - ci * 9;
        int chg = ci * 48 + cc;
        if (ci >= 8) chg = 384 + (ci - 8) * 48 + cc;
        sw[ci][j] = w_dw[chg * 9 + j];
    }
    if (threadIdx.x >= 144 && threadIdx.x < 160) {
        int ci = threadIdx.x - 144;
        int chg = ci * 48 + cc;
        if (ci >= 8) chg = 384 + (ci - 8) * 48 + cc;
        sbias[ci] = b_dw[chg];
    }
    __syncthreads();

    const int r = threadIdx.x >> 5;
    const int x0 = (threadIdx.x & 31) * 4;
    const int lane = threadIdx.x & 31;
    const int wid = threadIdx.x >> 5;

    // reduction scratch lives after the 16 planes (23040 bf16 = 46080 B used;
    // red needs 8*80*4 = 2560 B; reuse plane area after compute via sync).
    float qo[8][4];
    float aq[8];

    #pragma unroll
    for (int n = 0; n < 8; n++) {
        float v0[8];
        float v1[8];
        float v2[8];
        #pragma unroll
        for (int j = 0; j < 4; j++) {
            int base0 = (n * 10 + r) * 144 + 6 + x0 + 2 * j;
            float2 f0 = __bfloat1622float2(*(const __nv_bfloat162*)(sm + base0));
            float2 f1 = __bfloat1622float2(*(const __nv_bfloat162*)(sm + base0 + 144));
            float2 f2 = __bfloat1622float2(*(const __nv_bfloat162*)(sm + base0 + 288));
            v0[2 * j] = f0.x; v0[2 * j + 1] = f0.y;
            v1[2 * j] = f1.x; v1[2 * j + 1] = f1.y;
            v2[2 * j] = f2.x; v2[2 * j + 1] = f2.y;
        }
        float bi = sbias[n];
        float s = 0.f;
        #pragma unroll
        for (int i = 0; i < 4; i++) {
            float o = bi;
            o += sw[n][0] * v0[1 + i];
            o += sw[n][1] * v0[2 + i];
            o += sw[n][2] * v0[3 + i];
            o += sw[n][3] * v1[1 + i];
            o += sw[n][4] * v1[2 + i];
            o += sw[n][5] * v1[3 + i];
            o += sw[n][6] * v2[1 + i];
            o += sw[n][7] * v2[2 + i];
            o += sw[n][8] * v2[3 + i];
            qo[n][i] = o;
            s += o * o;
        }
        aq[n] = s;
    }

    // k channels: compute, then inline warp-reduce into per-warp smem slots.
    // red area placed at plane-15 end region is unsafe while planes are read,
    // so use a dedicated static array.
    __shared__ float red[8][80];

    #pragma unroll
    for (int m = 0; m < 8; m++) {
        float v0[8];
        float v1[8];
        float v2[8];
        #pragma unroll
        for (int j = 0; j < 4; j++) {
            int base0 = ((8 + m) * 10 + r) * 144 + 6 + x0 + 2 * j;
            float2 f0 = __bfloat1622float2(*(const __nv_bfloat162*)(sm + base0));
            float2 f1 = __bfloat1622float2(*(const __nv_bfloat162*)(sm + base0 + 144));
            float2 f2 = __bfloat1622float2(*(const __nv_bfloat162*)(sm + base0 + 288));
            v0[2 * j] = f0.x; v0[2 * j + 1] = f0.y;
            v1[2 * j] = f1.x; v1[2 * j + 1] = f1.y;
            v2[2 * j] = f2.x; v2[2 * j + 1] = f2.y;
        }
        float bi = sbias[8 + m];
        float ko[4];
        float sk = 0.f;
        #pragma unroll
        for (int i = 0; i < 4; i++) {
            float o = bi;
            o += sw[8 + m][0] * v0[1 + i];
            o += sw[8 + m][1] * v0[2 + i];
            o += sw[8 + m][2] * v0[3 + i];
            o += sw[8 + m][3] * v1[1 + i];
            o += sw[8 + m][4] * v1[2 + i];
            o += sw[8 + m][5] * v1[3 + i];
            o += sw[8 + m][6] * v2[1 + i];
            o += sw[8 + m][7] * v2[2 + i];
            o += sw[8 + m][8] * v2[3 + i];
            ko[i] = o;
            sk += o * o;
        }
        float skr = warp_red(sk);
        if (lane == 0) red[wid][72 + m] = skr;
        #pragma unroll
        for (int n = 0; n < 8; n++) {
            float a = qo[n][0] * ko[0] + qo[n][1] * ko[1] + qo[n][2] * ko[2] + qo[n][3] * ko[3];
            float ar_ = warp_red(a);
            if (lane == 0) red[wid][n * 8 + m] = ar_;
        }
    }
    #pragma unroll
    for (int n = 0; n < 8; n++) {
        float s1 = warp_red(aq[n]);
        if (lane == 0) red[wid][64 + n] = s1;
    }
    __syncthreads();
    if (threadIdx.x < 80) {
        float t = 0.f;
        #pragma unroll
        for (int w = 0; w < 8; w++) t += red[w][threadIdx.x];
        g_part[((size_t)b * NPART + cc * 16 + strip) * 80 + threadIdx.x] = t;
    }
}

// dwconv for v channels only -> g_vb (bf16)
__global__ __launch_bounds__(256) void k2v(
    const float* __restrict__ w_dw, const float* __restrict__ b_dw)
{
    const int chv = blockIdx.y;
    const int ch = 768 + chv;
    const int b = blockIdx.z;
    const int y0 = blockIdx.x * 16;

    __shared__ __align__(16) __nv_bfloat16 smv[18 * 144];
    const __nv_bfloat16* src = g_tmpb + ((size_t)b * QKV_CH + ch) * HW_;

    for (int idx = threadIdx.x; idx < 288; idx += 256) {
        int row = idx >> 4;
        int u = idx & 15;
        int gy = y0 - 1 + row;
        uint4 v;
        v.x = 0u; v.y = 0u; v.z = 0u; v.w = 0u;
        if (gy >= 0 && gy < 128) v = *(const uint4*)(src + gy * 128 + u * 8);
        *(uint4*)(smv + (row * 144 + 8 + u * 8)) = v;
    }
    if (threadIdx.x < 36) {
        int row = threadIdx.x >> 1;
        int col = 7;
        if (threadIdx.x & 1) col = 136;
        smv[row * 144 + col] = __float2bfloat16(0.f);
    }
    __syncthreads();

    float wv[9];
    #pragma unroll
    for (int i = 0; i < 9; i++) wv[i] = w_dw[ch * 9 + i];
    float bi = b_dw[ch];

    const int r = threadIdx.x >> 4;
    const int x0 = (threadIdx.x & 15) * 8;

    float v0[12];
    float v1[12];
    float v2[12];
    #pragma unroll
    for (int j = 0; j < 6; j++) {
        int base0 = r * 144 + 6 + x0 + 2 * j;
        float2 f0 = __bfloat1622float2(*(const __nv_bfloat162*)(smv + base0));
        float2 f1 = __bfloat1622float2(*(const __nv_bfloat162*)(smv + base0 + 144));
        float2 f2 = __bfloat1622float2(*(const __nv_bfloat162*)(smv + base0 + 288));
        v0[2 * j] = f0.x; v0[2 * j + 1] = f0.y;
        v1[2 * j] = f1.x; v1[2 * j + 1] = f1.y;
        v2[2 * j] = f2.x; v2[2 * j + 1] = f2.y;
    }

    float o[8];
    #pragma unroll
    for (int i = 0; i < 8; i++) {
        float t = bi;
        t += wv[0] * v0[1 + i];
        t += wv[1] * v0[2 + i];
        t += wv[2] * v0[3 + i];
        t += wv[3] * v1[1 + i];
        t += wv[4] * v1[2 + i];
        t += wv[5] * v1[3 + i];
        t += wv[6] * v2[1 + i];
        t += wv[7] * v2[2 + i];
        t += wv[8] * v2[3 + i];
        o[i] = t;
    }

    const int p = (y0 + r) * 128 + x0;
    __nv_bfloat162* dst = (__nv_bfloat162*)(g_vb + ((size_t)b * DIM + chv) * HW_ + p);
    dst[0] = __floats2bfloat162_rn(o[0], o[1]);
    dst[1] = __floats2bfloat162_rn(o[2], o[3]);
    dst[2] = __floats2bfloat162_rn(o[4], o[5]);
    dst[3] = __floats2bfloat162_rn(o[6], o[7]);
}

__global__ __launch_bounds__(640) void k4a_softmax(const float* __restrict__ temperature)
{
    const int b = blockIdx.x;
    __shared__ float red[80];

    const int e = threadIdx.x >> 3;
    const int j = threadIdx.x & 7;
    float t = 0.f;
    for (int s = j; s < NPART; s += 8)
        t += g_part[((size_t)b * NPART + s) * 80 + e];
    t += __shfl_down_sync(0xffffffffu, t, 4);
    t += __shfl_down_sync(0xffffffffu, t, 2);
    t += __shfl_down_sync(0xffffffffu, t, 1);
    if (j == 0) red[e] = t;
    __syncthreads();

    if (threadIdx.x < 8) {
        const int n = threadIdx.x;
        const float temp = temperature[0];
        float qn = fmaxf(sqrtf(red[64 + n]), 1e-12f);
        float logit[8];
        float mx = -1e30f;
        #pragma unroll
        for (int m = 0; m < 8; m++) {
            float kn = fmaxf(sqrtf(red[72 + m]), 1e-12f);
            float l = temp * red[n * 8 + m] / (qn * kn);
            logit[m] = l;
            mx = fmaxf(mx, l);
        }
        float sum = 0.f;
        float ex[8];
        #pragma unroll
        for (int m = 0; m < 8; m++) {
            ex[m] = expf(logit[m] - mx);
            sum += ex[m];
        }
        float inv = 1.f / sum;
        #pragma unroll
        for (int m = 0; m < 8; m++) g_attn[b * 64 + n * 8 + m] = ex[m] * inv;
    }
}

__global__ __launch_bounds__(256) void k4b_weff(const float* __restrict__ w_proj)
{
    const int b = blockIdx.y;
    __shared__ float at[64];
    if (threadIdx.x < 64) at[threadIdx.x] = g_attn[b * 64 + threadIdx.x];
    __syncthreads();

    const int idx = blockIdx.x * 256 + threadIdx.x;
    const int co = idx / DIM;
    const int jj = idx % DIM;
    const int m = jj / CC_;
    const int cc = jj % CC_;
    float s = 0.f;
    #pragma unroll
    for (int n = 0; n < 8; n++)
        s += at[n * 8 + m] * __ldg(&w_proj[co * DIM + n * CC_ + cc]);
    g_weffb[(size_t)b * DIM * DIM + idx] = __float2bfloat16(s);
}

extern "C" void kernel_launch(void* const* d_in, const int* in_sizes, int n_in,
                              void* d_out, int out_size)
{
    const float* x = (const float*)d_in[0];
    const float* temp = (const float*)d_in[1];
    const float* w_qkv = (const float*)d_in[2];
    const float* b_qkv = (const float*)d_in[3];
    const float* w_dw = (const float*)d_in[4];
    const float* b_dw = (const float*)d_in[5];
    const float* w_proj = (const float*)d_in[6];
    const float* b_proj = (const float*)d_in[7];
    float* out = (float*)d_out;

    int gcx = 24576;
    int gcw = 432;
    dim3 g1(128, 9, 4);
    dim3 gqk(16, 48, 4);
    dim3 gv(8, 384, 4);
    dim3 g4b(576, 4);
    dim3 g5(128, 3, 4);
    int nb4 = 4;

    kc_conv_x<<<gcx, 256>>>(x);
    kc_conv_w<<<gcw, 256>>>(w_qkv);
    k1_gemm<<<g1, 256>>>(b_qkv);
    k2qk<<<gqk, 256>>>(w_dw, b_dw);
    k2v<<<gv, 256>>>(w_dw, b_dw);
    k4a_softmax<<<nb4, 640>>>(temp);
    k4b_weff<<<g4b, 256>>>(w_proj);
    k5_gemm<<<g5, 256>>>(b_proj, x, out);
}